// round 4
// baseline (speedup 1.0000x reference)
#include <cuda_runtime.h>
#include <math.h>

#define ND 8000
#define NC 16000
#define FD 128
#define NH 4
#define OCD 128
#define ED_ 160000
#define EC_ 320000

// ------------------------- device scratch (no allocs allowed) -------------------------
__device__ __align__(16) float g_h[(size_t)ND * NH * FD];      // GEMM output h (max 8000x512)
__device__ __align__(16) float g_gcn[(size_t)NC * FD];
__device__ __align__(16) float g_gat[(size_t)NC * FD];
__device__ float g_deg[NC];
__device__ float g_dinv_d[ND];
__device__ float g_dinv_c[NC];
__device__ float g_asum[ND * NH];
__device__ float g_dsum[ND * NH];
__device__ float g_m[ND * NH];
__device__ float g_den[ND * NH];
__device__ float g_alpha[(ED_ + ND) * NH];
__device__ float g_scal[2];      // [0]=sum(ea), [1]=mean(ea)
__device__ float g_cvec[NH];     // per-head edge-attn coefficient
__device__ __align__(16) float g_l1d[(size_t)ND * FD];
__device__ __align__(16) float g_l2d[(size_t)ND * FD];
__device__ __align__(16) float g_l1c[(size_t)NC * FD];
__device__ __align__(16) float g_l2c[(size_t)NC * FD];
__device__ __align__(16) float g_cat[(size_t)NC * 2 * FD];
__device__ __align__(16) float g_dfea[(size_t)ND * OCD];
__device__ __align__(16) float g_cfea[(size_t)NC * OCD];
// CSR scratch (rebuilt per graph; offs/cnt/cursor shared since graphs processed sequentially)
__device__ int g_cnt[NC];
__device__ int g_offs[NC + 1];
__device__ int g_cursor[NC];
__device__ int g_eid_d[ED_];
__device__ int g_eid_c[EC_];

// ------------------------- helpers -------------------------
__device__ __forceinline__ float warp_sum(float v) {
#pragma unroll
    for (int o = 16; o; o >>= 1) v += __shfl_down_sync(0xffffffffu, v, o);
    return v;
}

// float atomic max via signed-max / unsigned-min bit tricks (correct incl. -inf init)
__device__ __forceinline__ void atomic_max_f(float* addr, float v) {
    if (v >= 0.f) atomicMax((int*)addr, __float_as_int(v));
    else          atomicMin((unsigned int*)addr, (unsigned int)__float_as_int(v));
}

// ------------------------- small utility kernels -------------------------
__global__ void k_fill(float* p, float v, long n) {
    long i = (long)blockIdx.x * blockDim.x + threadIdx.x;
    if (i < n) p[i] = v;
}

__global__ void k_ifill(int* p, int v, long n) {
    long i = (long)blockIdx.x * blockDim.x + threadIdx.x;
    if (i < n) p[i] = v;
}

__global__ void k_copy(const float* __restrict__ a, float* __restrict__ o, long n) {
    long i = (long)blockIdx.x * blockDim.x + threadIdx.x;
    if (i < n) o[i] = a[i];
}

__global__ void k_sum(const float* __restrict__ w, float* out, int n) {
    float s = 0.f;
    for (int i = blockIdx.x * blockDim.x + threadIdx.x; i < n; i += gridDim.x * blockDim.x)
        s += w[i];
    s = warp_sum(s);
    __shared__ float sh[8];
    int l = threadIdx.x & 31, wi = threadIdx.x >> 5;
    if (!l) sh[wi] = s;
    __syncthreads();
    if (threadIdx.x < 8) {
        float v = sh[threadIdx.x];
#pragma unroll
        for (int o = 4; o; o >>= 1) v += __shfl_down_sync(0xffu, v, o);
        if (!threadIdx.x) atomicAdd(out, v);
    }
}

// c[hd] = sum_f We[0,hd*F+f]*ae[hd,f];  scal[1] = scal[0]/E
__global__ void k_gat_prep(const float* __restrict__ We, const float* __restrict__ ae,
                           float* scal, float* cvec, float inv_e) {
    int wi = threadIdx.x >> 5, l = threadIdx.x & 31;
    if (wi < NH) {
        float4 a = ((const float4*)We)[wi * 32 + l];
        float4 b = ((const float4*)ae)[wi * 32 + l];
        float s = a.x * b.x + a.y * b.y + a.z * b.z + a.w * b.w;
        s = warp_sum(s);
        if (!l) cvec[wi] = s;
    }
    if (threadIdx.x == 0) scal[1] = scal[0] * inv_e;
}

__global__ void k_deg(const int* __restrict__ dst, const float* __restrict__ w, float* deg, int E) {
    int i = blockIdx.x * blockDim.x + threadIdx.x;
    if (i < E) atomicAdd(&deg[dst[i]], w[i]);
}

__global__ void k_dinv(const float* __restrict__ deg, float* dinv, int n) {
    int i = blockIdx.x * blockDim.x + threadIdx.x;
    if (i < n) { float d = deg[i]; dinv[i] = d > 0.f ? rsqrtf(d) : 0.f; }
}

// ------------------------- CSR build (per graph, by destination) -------------------------
__global__ void k_hist(const int* __restrict__ dst, int* __restrict__ cnt, int E) {
    int i = blockIdx.x * blockDim.x + threadIdx.x;
    if (i < E) atomicAdd(&cnt[dst[i]], 1);
}

// single-block exclusive scan over cnt[0..n) -> offs, cursor; offs[n] = total
__global__ void k_scan(const int* __restrict__ cnt, int* __restrict__ offs,
                       int* __restrict__ cursor, int n) {
    __shared__ int tmp[1024];
    __shared__ int carry_s;
    int tid = threadIdx.x;
    if (tid == 0) carry_s = 0;
    __syncthreads();
    for (int base = 0; base < n; base += 1024) {
        int v = (base + tid < n) ? cnt[base + tid] : 0;
        tmp[tid] = v;
        __syncthreads();
        int incl = v;
#pragma unroll
        for (int off = 1; off < 1024; off <<= 1) {
            int t = (tid >= off) ? tmp[tid - off] : 0;
            __syncthreads();
            tmp[tid] = incl = incl + t;
            __syncthreads();
        }
        int carry = carry_s;
        if (base + tid < n) {
            int ex = carry + incl - v;
            offs[base + tid] = ex;
            cursor[base + tid] = ex;
        }
        __syncthreads();
        if (tid == 1023) carry_s = carry + incl;  // lane 1023's incl = chunk total (zero-padded)
        __syncthreads();
    }
    if (tid == 0) offs[n] = carry_s;
}

__global__ void k_place(const int* __restrict__ dst, int* __restrict__ cursor,
                        int* __restrict__ eid, int E) {
    int i = blockIdx.x * blockDim.x + threadIdx.x;
    if (i < E) {
        int pos = atomicAdd(&cursor[dst[i]], 1);
        eid[pos] = i;
    }
}

// ------------------------- GCN gather (warp per destination node) -------------------------
// out[d,:] = dinv[d]^2 * h[d,:] + sum_in-edges dinv[s]*w*dinv[d] * h[s,:]
__global__ void k_gcn_gather(const float* __restrict__ h, const int* __restrict__ src,
                             const float* __restrict__ ew, const float* __restrict__ dinv,
                             const int* __restrict__ offs, const int* __restrict__ eid,
                             float* __restrict__ out, int n) {
    int t = blockIdx.x * blockDim.x + threadIdx.x;
    int d = t >> 5, lane = t & 31;
    if (d >= n) return;
    float dv = dinv[d];
    float4 acc = ((const float4*)(h + (size_t)d * FD))[lane];
    float c0 = dv * dv;
    acc.x *= c0; acc.y *= c0; acc.z *= c0; acc.w *= c0;
    int b = offs[d], e_end = offs[d + 1];
    for (int i = b; i < e_end; ++i) {
        int e = eid[i];
        int s = src[e];
        float c = dinv[s] * ew[e] * dv;
        float4 v = ((const float4*)(h + (size_t)s * FD))[lane];
        acc.x += c * v.x; acc.y += c * v.y; acc.z += c * v.z; acc.w += c * v.w;
    }
    ((float4*)(out + (size_t)d * FD))[lane] = acc;
}

// ------------------------- GAT -------------------------
// one warp per (node, head): asum/dsum dot products
__global__ void k_gat_node(const float* __restrict__ h, const float* __restrict__ as_,
                           const float* __restrict__ ad_, float* asum, float* dsum,
                           int nH, int H) {
    int t = blockIdx.x * blockDim.x + threadIdx.x;
    int w = t >> 5, lane = t & 31;
    if (w >= nH) return;
    int hd = w % H;
    float4 hv = ((const float4*)h)[(size_t)w * 32 + lane];
    float4 sv = ((const float4*)as_)[hd * 32 + lane];
    float4 dv = ((const float4*)ad_)[hd * 32 + lane];
    float a = hv.x * sv.x + hv.y * sv.y + hv.z * sv.z + hv.w * sv.w;
    float b = hv.x * dv.x + hv.y * dv.y + hv.z * dv.z + hv.w * dv.w;
    a = warp_sum(a);
    b = warp_sum(b);
    if (!lane) { asum[w] = a; dsum[w] = b; }
}

// alpha + leaky_relu, atomic segment max over destination. edges [0,E) real, [E,E+n) self-loops
__global__ void k_gat_alpha(const int* __restrict__ src, const int* __restrict__ dst,
                            const float* __restrict__ ew, const float* __restrict__ scal,
                            const float* __restrict__ cvec, const float* __restrict__ asum,
                            const float* __restrict__ dsum, float* __restrict__ alpha,
                            float* __restrict__ m, int E, int n, int H) {
    int idx = blockIdx.x * blockDim.x + threadIdx.x;
    if (idx >= (E + n) * H) return;
    int e = idx / H, hd = idx - e * H;
    int s, d;
    if (e < E) { s = src[e]; d = dst[e]; } else { s = e - E; d = s; }
    float a = asum[s * H + hd] + dsum[d * H + hd];
    if (cvec) {
        float ea = (e < E) ? ew[e] : scal[1];
        a += ea * cvec[hd];
    }
    a = a > 0.f ? a : 0.2f * a;   // leaky_relu 0.2
    alpha[idx] = a;
    atomic_max_f(&m[d * H + hd], a);
}

__global__ void k_gat_exp(const int* __restrict__ dst, float* __restrict__ alpha,
                          const float* __restrict__ m, float* __restrict__ den,
                          int E, int n, int H) {
    int idx = blockIdx.x * blockDim.x + threadIdx.x;
    if (idx >= (E + n) * H) return;
    int e = idx / H, hd = idx - e * H;
    int d = (e < E) ? dst[e] : (e - E);
    float p = __expf(alpha[idx] - m[d * H + hd]);
    alpha[idx] = p;
    atomicAdd(&den[d * H + hd], p);
}

// warp per destination node; accumulates ALL heads into one float4/lane
// (mean over heads shares the feature index), writes out row once.
template <int H>
__global__ void k_gat_gather(const float* __restrict__ h, const int* __restrict__ src,
                             const float* __restrict__ alpha, const float* __restrict__ den,
                             const int* __restrict__ offs, const int* __restrict__ eid,
                             float* __restrict__ out, int n, int E) {
    int t = blockIdx.x * blockDim.x + threadIdx.x;
    int d = t >> 5, lane = t & 31;
    if (d >= n) return;
    float rden[H];
#pragma unroll
    for (int hd = 0; hd < H; hd++) rden[hd] = 1.f / den[d * H + hd];
    float4 acc = make_float4(0.f, 0.f, 0.f, 0.f);
#pragma unroll
    for (int hd = 0; hd < H; hd++) {   // self-loop term
        float c = alpha[(size_t)(E + d) * H + hd] * rden[hd];
        float4 v = ((const float4*)(h + ((size_t)d * H + hd) * FD))[lane];
        acc.x += c * v.x; acc.y += c * v.y; acc.z += c * v.z; acc.w += c * v.w;
    }
    int b = offs[d], e_end = offs[d + 1];
    for (int i = b; i < e_end; ++i) {
        int e = eid[i];
        int s = src[e];
#pragma unroll
        for (int hd = 0; hd < H; hd++) {
            float c = alpha[(size_t)e * H + hd] * rden[hd];
            float4 v = ((const float4*)(h + ((size_t)s * H + hd) * FD))[lane];
            acc.x += c * v.x; acc.y += c * v.y; acc.z += c * v.z; acc.w += c * v.w;
        }
    }
    const float invH = 1.f / (float)H;
    acc.x *= invH; acc.y *= invH; acc.z *= invH; acc.w *= invH;
    ((float4*)(out + (size_t)d * FD))[lane] = acc;
}

// l = relu((gcn + bg + gat + ba)/2)
__global__ void k_combine(const float* __restrict__ gcn, const float* __restrict__ gat,
                          const float* __restrict__ bg, const float* __restrict__ ba,
                          float* __restrict__ o, long n128) {
    long i = (long)blockIdx.x * blockDim.x + threadIdx.x;
    if (i < n128) {
        int f = (int)(i & (FD - 1));
        float v = (gcn[i] + bg[f] + gat[i] + ba[f]) * 0.5f;
        o[i] = v > 0.f ? v : 0.f;
    }
}

// cat[n, 0:128]=a row, cat[n, 128:256]=b row
__global__ void k_cat(const float* __restrict__ a, const float* __restrict__ b,
                      float* __restrict__ o, long n256) {
    long i = (long)blockIdx.x * blockDim.x + threadIdx.x;
    if (i < n256) {
        long node = i >> 8;
        int f = (int)(i & 255);
        o[i] = (f < FD) ? a[node * FD + f] : b[node * FD + (f - FD)];
    }
}

// ------------------------- tiled SGEMM (double-buffered) -------------------------
// C[M,N] = A[M,K] @ op(B) (+bias[n]); TB=0: B is [K,N] row-major; TB=1: B is [N,K] row-major.
// BM=BN=128, BK=16, 256 threads, 8x8 per thread. Ping-pong smem + register-staged
// global prefetch, single __syncthreads() per K-chunk. K must be a multiple of 16.
template <bool TB>
__global__ __launch_bounds__(256, 2) void k_sgemm(const float* __restrict__ A,
                                                  const float* __restrict__ B,
                                                  float* __restrict__ C, int M, int N, int K,
                                                  const float* __restrict__ bias) {
    __shared__ float As[2][16][128];
    __shared__ float Bs[2][16][128];
    const int m0 = blockIdx.y * 128;
    const int n0 = blockIdx.x * 128;
    const int tid = threadIdx.x;
    const int tx = tid & 15, ty = tid >> 4;
    const int rA = tid >> 2;          // 0..63
    const int kq = (tid & 3) << 2;    // 0,4,8,12
    const int kr = tid >> 5;          // 0..7   (TB=false B path)
    const int c4 = (tid & 31) << 2;   // 0..124 (TB=false B path)
    float acc[8][8] = {};
    float4 va[2], vb[2];

    auto load_tile = [&](int k0) {
#pragma unroll
        for (int hh = 0; hh < 2; hh++) {
            int gm = m0 + rA + hh * 64;
            va[hh] = make_float4(0.f, 0.f, 0.f, 0.f);
            if (gm < M) va[hh] = *(const float4*)(A + (size_t)gm * K + k0 + kq);
        }
        if (TB) {
#pragma unroll
            for (int hh = 0; hh < 2; hh++) {
                int gn = n0 + rA + hh * 64;
                vb[hh] = make_float4(0.f, 0.f, 0.f, 0.f);
                if (gn < N) vb[hh] = *(const float4*)(B + (size_t)gn * K + k0 + kq);
            }
        } else {
#pragma unroll
            for (int hh = 0; hh < 2; hh++) {
                int kk = kr + hh * 8;
                int gn = n0 + c4;
                float4 v = make_float4(0.f, 0.f, 0.f, 0.f);
                if (gn + 3 < N) {
                    v = *(const float4*)(B + (size_t)(k0 + kk) * N + gn);
                } else {
                    if (gn + 0 < N) v.x = B[(size_t)(k0 + kk) * N + gn + 0];
                    if (gn + 1 < N) v.y = B[(size_t)(k0 + kk) * N + gn + 1];
                    if (gn + 2 < N) v.z = B[(size_t)(k0 + kk) * N + gn + 2];
                    if (gn + 3 < N) v.w = B[(size_t)(k0 + kk) * N + gn + 3];
                }
                vb[hh] = v;
            }
        }
    };
    auto store_tile = [&](int buf) {
#pragma unroll
        for (int hh = 0; hh < 2; hh++) {
            int mm = rA + hh * 64;
            As[buf][kq + 0][mm] = va[hh].x; As[buf][kq + 1][mm] = va[hh].y;
            As[buf][kq + 2][mm] = va[hh].z; As[buf][kq + 3][mm] = va[hh].w;
        }
        if (TB) {
#pragma unroll
            for (int hh = 0; hh < 2; hh++) {
                int nn = rA + hh * 64;
                Bs[buf][kq + 0][nn] = vb[hh].x; Bs[buf][kq + 1][nn] = vb[hh].y;
                Bs[buf][kq + 2][nn] = vb[hh].z; Bs[buf][kq + 3][nn] = vb[hh].w;
            }
        } else {
#pragma unroll
            for (int hh = 0; hh < 2; hh++) {
                int kk = kr + hh * 8;
                Bs[buf][kk][c4 + 0] = vb[hh].x; Bs[buf][kk][c4 + 1] = vb[hh].y;
                Bs[buf][kk][c4 + 2] = vb[hh].z; Bs[buf][kk][c4 + 3] = vb[hh].w;
            }
        }
    };

    const int nk = K >> 4;
    load_tile(0);
    int buf = 0;
    for (int it = 0; it < nk; ++it) {
        store_tile(buf);
        __syncthreads();
        if (it + 1 < nk) load_tile((it + 1) << 4);   // overlap next global load with compute
#pragma unroll
        for (int k = 0; k < 16; k++) {
            float a[8], b[8];
            *(float4*)(a)     = *(const float4*)(&As[buf][k][ty * 8]);
            *(float4*)(a + 4) = *(const float4*)(&As[buf][k][ty * 8 + 4]);
            *(float4*)(b)     = *(const float4*)(&Bs[buf][k][tx * 8]);
            *(float4*)(b + 4) = *(const float4*)(&Bs[buf][k][tx * 8 + 4]);
#pragma unroll
            for (int i = 0; i < 8; i++)
#pragma unroll
                for (int j = 0; j < 8; j++)
                    acc[i][j] += a[i] * b[j];
        }
        buf ^= 1;
        // next iteration writes the OTHER buffer; per-iteration barrier bounds skew.
    }
#pragma unroll
    for (int i = 0; i < 8; i++) {
        int gm = m0 + ty * 8 + i;
        if (gm >= M) continue;
#pragma unroll
        for (int j = 0; j < 8; j += 4) {
            int gn = n0 + tx * 8 + j;
            if (gn + 3 < N) {
                float4 v = make_float4(acc[i][j], acc[i][j + 1], acc[i][j + 2], acc[i][j + 3]);
                if (bias) { v.x += bias[gn]; v.y += bias[gn + 1]; v.z += bias[gn + 2]; v.w += bias[gn + 3]; }
                *(float4*)(C + (size_t)gm * N + gn) = v;
            } else {
                for (int q = 0; q < 4; q++) {
                    int g = gn + q;
                    if (g < N) {
                        float v = acc[i][j + q];
                        if (bias) v += bias[g];
                        C[(size_t)gm * N + g] = v;
                    }
                }
            }
        }
    }
}

// ------------------------- host orchestration -------------------------
static inline unsigned gb(long n, int t) { return (unsigned)((n + t - 1) / t); }

extern "C" void kernel_launch(void* const* d_in, const int* in_sizes, int n_in,
                              void* d_out, int out_size) {
    (void)in_sizes; (void)n_in; (void)out_size;
    const float* x_drug = (const float*)d_in[0];
    const float* x_cir  = (const float*)d_in[1];
    const int*   dei    = (const int*)d_in[2];
    const int*   cei    = (const int*)d_in[3];
    const float* dew    = (const float*)d_in[4];
    const float* cew    = (const float*)d_in[5];
    const float* Wg1_d = (const float*)d_in[6];  const float* bg1_d = (const float*)d_in[7];
    const float* Wg2_d = (const float*)d_in[8];  const float* bg2_d = (const float*)d_in[9];
    const float* Wa_d  = (const float*)d_in[10]; const float* as_d  = (const float*)d_in[11];
    const float* ad_d  = (const float*)d_in[12]; const float* We_d  = (const float*)d_in[13];
    const float* ae_d  = (const float*)d_in[14]; const float* ba_d  = (const float*)d_in[15];
    const float* Wg1_c = (const float*)d_in[16]; const float* bg1_c = (const float*)d_in[17];
    const float* Wg2_c = (const float*)d_in[18]; const float* bg2_c = (const float*)d_in[19];
    const float* Wa_c  = (const float*)d_in[20]; const float* as_c  = (const float*)d_in[21];
    const float* ad_c  = (const float*)d_in[22]; const float* ba_c  = (const float*)d_in[23];
    const float* Kd    = (const float*)d_in[24]; const float* bKd   = (const float*)d_in[25];
    const float* Kc    = (const float*)d_in[26]; const float* bKc   = (const float*)d_in[27];
    float* out = (float*)d_out;

    const int* src_d = dei;       const int* dst_d = dei + ED_;
    const int* src_c = cei;       const int* dst_c = cei + EC_;

    float *p_h, *p_gcn, *p_gat, *p_deg, *p_dinv_d, *p_dinv_c, *p_asum, *p_dsum;
    float *p_m, *p_den, *p_alpha, *p_scal, *p_cvec;
    float *p_l1d, *p_l2d, *p_l1c, *p_l2c, *p_cat, *p_dfea, *p_cfea;
    int *p_cnt, *p_offs, *p_cursor, *p_eid_d, *p_eid_c;
    cudaGetSymbolAddress((void**)&p_h, g_h);
    cudaGetSymbolAddress((void**)&p_gcn, g_gcn);
    cudaGetSymbolAddress((void**)&p_gat, g_gat);
    cudaGetSymbolAddress((void**)&p_deg, g_deg);
    cudaGetSymbolAddress((void**)&p_dinv_d, g_dinv_d);
    cudaGetSymbolAddress((void**)&p_dinv_c, g_dinv_c);
    cudaGetSymbolAddress((void**)&p_asum, g_asum);
    cudaGetSymbolAddress((void**)&p_dsum, g_dsum);
    cudaGetSymbolAddress((void**)&p_m, g_m);
    cudaGetSymbolAddress((void**)&p_den, g_den);
    cudaGetSymbolAddress((void**)&p_alpha, g_alpha);
    cudaGetSymbolAddress((void**)&p_scal, g_scal);
    cudaGetSymbolAddress((void**)&p_cvec, g_cvec);
    cudaGetSymbolAddress((void**)&p_l1d, g_l1d);
    cudaGetSymbolAddress((void**)&p_l2d, g_l2d);
    cudaGetSymbolAddress((void**)&p_l1c, g_l1c);
    cudaGetSymbolAddress((void**)&p_l2c, g_l2c);
    cudaGetSymbolAddress((void**)&p_cat, g_cat);
    cudaGetSymbolAddress((void**)&p_dfea, g_dfea);
    cudaGetSymbolAddress((void**)&p_cfea, g_cfea);
    cudaGetSymbolAddress((void**)&p_cnt, g_cnt);
    cudaGetSymbolAddress((void**)&p_offs, g_offs);
    cudaGetSymbolAddress((void**)&p_cursor, g_cursor);
    cudaGetSymbolAddress((void**)&p_eid_d, g_eid_d);
    cudaGetSymbolAddress((void**)&p_eid_c, g_eid_c);

    auto fill = [](float* p, float v, long n) {
        k_fill<<<gb(n, 256), 256>>>(p, v, n);
    };
    auto gemm_nn = [](const float* A, const float* B, float* C, int M, int N, int K,
                      const float* bias) {
        dim3 grid((N + 127) / 128, (M + 127) / 128);
        k_sgemm<false><<<grid, 256>>>(A, B, C, M, N, K, bias);
    };
    auto build_csr = [&](const int* dst, int E, int n, int* eid) {
        k_ifill<<<gb(n, 256), 256>>>(p_cnt, 0, n);
        k_hist<<<gb(E, 256), 256>>>(dst, p_cnt, E);
        k_scan<<<1, 1024>>>(p_cnt, p_offs, p_cursor, n);
        k_place<<<gb(E, 256), 256>>>(dst, p_cursor, eid, E);
    };

    auto run_gcn = [&](const float* x, const float* Wg, const int* src,
                       const float* ew, const float* dinv, const int* eid,
                       float* outb, int n) {
        gemm_nn(x, Wg, p_h, n, FD, FD, nullptr);
        k_gcn_gather<<<gb((long)n * 32, 256), 256>>>(p_h, src, ew, dinv, p_offs, eid, outb, n);
    };

    auto run_gat = [&](const float* x, const float* Wa, const float* as_, const float* ad_,
                       const int* src, const int* dst, const float* ew, bool edge_attr,
                       const int* eid, float* outb, int n, int E, int H) {
        gemm_nn(x, Wa, p_h, n, H * FD, FD, nullptr);
        int nH = n * H;
        k_gat_node<<<gb((long)nH * 32, 256), 256>>>(p_h, as_, ad_, p_asum, p_dsum, nH, H);
        fill(p_m, -INFINITY, nH);
        fill(p_den, 0.f, nH);
        long tot = (long)(E + n) * H;
        k_gat_alpha<<<gb(tot, 256), 256>>>(src, dst, ew, p_scal, edge_attr ? p_cvec : nullptr,
                                           p_asum, p_dsum, p_alpha, p_m, E, n, H);
        k_gat_exp<<<gb(tot, 256), 256>>>(dst, p_alpha, p_m, p_den, E, n, H);
        if (H == 4)
            k_gat_gather<4><<<gb((long)n * 32, 256), 256>>>(p_h, src, p_alpha, p_den,
                                                            p_offs, eid, outb, n, E);
        else
            k_gat_gather<1><<<gb((long)n * 32, 256), 256>>>(p_h, src, p_alpha, p_den,
                                                            p_offs, eid, outb, n, E);
    };

    auto combine = [&](const float* bg, const float* ba, float* l, int n) {
        long n128 = (long)n * FD;
        k_combine<<<gb(n128, 256), 256>>>(p_gcn, p_gat, bg, ba, l, n128);
    };

    // ---- per-graph invariants: degree / symmetric-norm; edge-attn mean + coeffs ----
    fill(p_deg, 1.f, ND);                                    // self-loop weight 1
    k_deg<<<gb(ED_, 256), 256>>>(dst_d, dew, p_deg, ED_);
    k_dinv<<<gb(ND, 256), 256>>>(p_deg, p_dinv_d, ND);
    fill(p_deg, 1.f, NC);
    k_deg<<<gb(EC_, 256), 256>>>(dst_c, cew, p_deg, EC_);
    k_dinv<<<gb(NC, 256), 256>>>(p_deg, p_dinv_c, NC);
    fill(p_scal, 0.f, 2);
    k_sum<<<256, 256>>>(dew, p_scal, ED_);
    k_gat_prep<<<1, 128>>>(We_d, ae_d, p_scal, p_cvec, 1.f / (float)ED_);

    // ---- drug graph: CSR + 2 layers ----
    build_csr(dst_d, ED_, ND, p_eid_d);
    run_gcn(x_drug, Wg1_d, src_d, dew, p_dinv_d, p_eid_d, p_gcn, ND);
    run_gat(x_drug, Wa_d, as_d, ad_d, src_d, dst_d, dew, true, p_eid_d, p_gat, ND, ED_, NH);
    combine(bg1_d, ba_d, p_l1d, ND);
    run_gcn(p_l1d, Wg2_d, src_d, dew, p_dinv_d, p_eid_d, p_gcn, ND);
    run_gat(p_l1d, Wa_d, as_d, ad_d, src_d, dst_d, dew, true, p_eid_d, p_gat, ND, ED_, NH);
    combine(bg2_d, ba_d, p_l2d, ND);

    // ---- circ graph: CSR (offs rebuilt) + 2 layers ----
    build_csr(dst_c, EC_, NC, p_eid_c);
    run_gcn(x_cir, Wg1_c, src_c, cew, p_dinv_c, p_eid_c, p_gcn, NC);
    run_gat(x_cir, Wa_c, as_c, ad_c, src_c, dst_c, nullptr, false, p_eid_c, p_gat, NC, EC_, 1);
    combine(bg1_c, ba_c, p_l1c, NC);
    run_gcn(p_l1c, Wg2_c, src_c, cew, p_dinv_c, p_eid_c, p_gcn, NC);
    run_gat(p_l1c, Wa_c, as_c, ad_c, src_c, dst_c, nullptr, false, p_eid_c, p_gat, NC, EC_, 1);
    combine(bg2_c, ba_c, p_l2c, NC);

    // ---- CNN fuse: fea = [l1 | l2] @ Kflat^T + bK   (Kflat is [OC, 2F] row-major) ----
    k_cat<<<gb((long)ND * 256, 256), 256>>>(p_l1d, p_l2d, p_cat, (long)ND * 256);
    {
        dim3 grid((OCD + 127) / 128, (ND + 127) / 128);
        k_sgemm<true><<<grid, 256>>>(p_cat, Kd, p_dfea, ND, OCD, 2 * FD, bKd);
    }
    k_cat<<<gb((long)NC * 256, 256), 256>>>(p_l1c, p_l2c, p_cat, (long)NC * 256);
    {
        dim3 grid((OCD + 127) / 128, (NC + 127) / 128);
        k_sgemm<true><<<grid, 256>>>(p_cat, Kc, p_cfea, NC, OCD, 2 * FD, bKc);
    }

    // ---- final: out[0 : NC*ND] = cir_fea @ drug_fea^T ; tail = drug_fea ----
    {
        dim3 grid((ND + 127) / 128, (NC + 127) / 128);
        k_sgemm<true><<<grid, 256>>>(p_cfea, p_dfea, out, NC, ND, FD, nullptr);
    }
    long tail = (long)ND * OCD;
    k_copy<<<gb(tail, 256), 256>>>(p_dfea, out + (size_t)NC * ND, tail);
}

// round 7
// speedup vs baseline: 1.4912x; 1.4912x over previous
#include <cuda_runtime.h>
#include <math.h>

#define ND 8000
#define NC 16000
#define FD 128
#define NH 4
#define OCD 128
#define ED_ 160000
#define EC_ 320000

// ------------------------- device scratch (no allocs allowed) -------------------------
__device__ __align__(16) float g_h[(size_t)ND * NH * FD];      // GEMM output h (max 8000x512)
__device__ __align__(16) float g_gcn[(size_t)NC * FD];
__device__ __align__(16) float g_gat[(size_t)NC * FD];
__device__ float g_deg[NC];
__device__ float g_dinv_d[ND];
__device__ float g_dinv_c[NC];
__device__ float g_asum[ND * NH];
__device__ float g_dsum[ND * NH];
__device__ float g_m[ND * NH];
__device__ float g_den[ND * NH];
__device__ float g_alpha[(ED_ + ND) * NH];
__device__ float g_scal[2];      // [0]=sum(ea), [1]=mean(ea)
__device__ float g_cvec[NH];     // per-head edge-attn coefficient
__device__ __align__(16) float g_l1d[(size_t)ND * FD];
__device__ __align__(16) float g_l2d[(size_t)ND * FD];
__device__ __align__(16) float g_l1c[(size_t)NC * FD];
__device__ __align__(16) float g_l2c[(size_t)NC * FD];
__device__ __align__(16) float g_cat[(size_t)NC * 2 * FD];
__device__ __align__(16) float g_dfea[(size_t)ND * OCD];
__device__ __align__(16) float g_cfea[(size_t)NC * OCD];
// CSR scratch (rebuilt per graph; offs/cnt/cursor shared since graphs processed sequentially)
__device__ int g_cnt[NC];
__device__ int g_offs[NC + 1];
__device__ int g_cursor[NC];
__device__ int g_eid_d[ED_];
__device__ int g_eid_c[EC_];

// ------------------------- helpers -------------------------
__device__ __forceinline__ float warp_sum(float v) {
#pragma unroll
    for (int o = 16; o; o >>= 1) v += __shfl_down_sync(0xffffffffu, v, o);
    return v;
}

// float atomic max via signed-max / unsigned-min bit tricks (correct incl. -inf init)
__device__ __forceinline__ void atomic_max_f(float* addr, float v) {
    if (v >= 0.f) atomicMax((int*)addr, __float_as_int(v));
    else          atomicMin((unsigned int*)addr, (unsigned int)__float_as_int(v));
}

__device__ __forceinline__ unsigned f2tf32(float x) {
    unsigned r;
    asm("cvt.rna.tf32.f32 %0, %1;" : "=r"(r) : "f"(x));
    return r;
}

__device__ __forceinline__ void mma_tf32(float* c, unsigned a0, unsigned a1, unsigned a2,
                                         unsigned a3, unsigned b0, unsigned b1) {
    asm volatile("mma.sync.aligned.m16n8k8.row.col.f32.tf32.tf32.f32 "
                 "{%0,%1,%2,%3}, {%4,%5,%6,%7}, {%8,%9}, {%0,%1,%2,%3};"
                 : "+f"(c[0]), "+f"(c[1]), "+f"(c[2]), "+f"(c[3])
                 : "r"(a0), "r"(a1), "r"(a2), "r"(a3), "r"(b0), "r"(b1));
}

// ------------------------- small utility kernels -------------------------
__global__ void k_fill(float* p, float v, long n) {
    long i = (long)blockIdx.x * blockDim.x + threadIdx.x;
    if (i < n) p[i] = v;
}

__global__ void k_ifill(int* p, int v, long n) {
    long i = (long)blockIdx.x * blockDim.x + threadIdx.x;
    if (i < n) p[i] = v;
}

__global__ void k_copy(const float* __restrict__ a, float* __restrict__ o, long n) {
    long i = (long)blockIdx.x * blockDim.x + threadIdx.x;
    if (i < n) o[i] = a[i];
}

__global__ void k_sum(const float* __restrict__ w, float* out, int n) {
    float s = 0.f;
    for (int i = blockIdx.x * blockDim.x + threadIdx.x; i < n; i += gridDim.x * blockDim.x)
        s += w[i];
    s = warp_sum(s);
    __shared__ float sh[8];
    int l = threadIdx.x & 31, wi = threadIdx.x >> 5;
    if (!l) sh[wi] = s;
    __syncthreads();
    if (threadIdx.x < 8) {
        float v = sh[threadIdx.x];
#pragma unroll
        for (int o = 4; o; o >>= 1) v += __shfl_down_sync(0xffu, v, o);
        if (!threadIdx.x) atomicAdd(out, v);
    }
}

// c[hd] = sum_f We[0,hd*F+f]*ae[hd,f];  scal[1] = scal[0]/E
__global__ void k_gat_prep(const float* __restrict__ We, const float* __restrict__ ae,
                           float* scal, float* cvec, float inv_e) {
    int wi = threadIdx.x >> 5, l = threadIdx.x & 31;
    if (wi < NH) {
        float4 a = ((const float4*)We)[wi * 32 + l];
        float4 b = ((const float4*)ae)[wi * 32 + l];
        float s = a.x * b.x + a.y * b.y + a.z * b.z + a.w * b.w;
        s = warp_sum(s);
        if (!l) cvec[wi] = s;
    }
    if (threadIdx.x == 0) scal[1] = scal[0] * inv_e;
}

__global__ void k_deg(const int* __restrict__ dst, const float* __restrict__ w, float* deg, int E) {
    int i = blockIdx.x * blockDim.x + threadIdx.x;
    if (i < E) atomicAdd(&deg[dst[i]], w[i]);
}

__global__ void k_dinv(const float* __restrict__ deg, float* dinv, int n) {
    int i = blockIdx.x * blockDim.x + threadIdx.x;
    if (i < n) { float d = deg[i]; dinv[i] = d > 0.f ? rsqrtf(d) : 0.f; }
}

// ------------------------- CSR build (per graph, by destination) -------------------------
__global__ void k_hist(const int* __restrict__ dst, int* __restrict__ cnt, int E) {
    int i = blockIdx.x * blockDim.x + threadIdx.x;
    if (i < E) atomicAdd(&cnt[dst[i]], 1);
}

// single-block exclusive scan over cnt[0..n) -> offs, cursor; offs[n] = total
__global__ void k_scan(const int* __restrict__ cnt, int* __restrict__ offs,
                       int* __restrict__ cursor, int n) {
    __shared__ int tmp[1024];
    __shared__ int carry_s;
    int tid = threadIdx.x;
    if (tid == 0) carry_s = 0;
    __syncthreads();
    for (int base = 0; base < n; base += 1024) {
        int v = (base + tid < n) ? cnt[base + tid] : 0;
        tmp[tid] = v;
        __syncthreads();
        int incl = v;
#pragma unroll
        for (int off = 1; off < 1024; off <<= 1) {
            int t = (tid >= off) ? tmp[tid - off] : 0;
            __syncthreads();
            tmp[tid] = incl = incl + t;
            __syncthreads();
        }
        int carry = carry_s;
        if (base + tid < n) {
            int ex = carry + incl - v;
            offs[base + tid] = ex;
            cursor[base + tid] = ex;
        }
        __syncthreads();
        if (tid == 1023) carry_s = carry + incl;  // lane 1023's incl = chunk total (zero-padded)
        __syncthreads();
    }
    if (tid == 0) offs[n] = carry_s;
}

__global__ void k_place(const int* __restrict__ dst, int* __restrict__ cursor,
                        int* __restrict__ eid, int E) {
    int i = blockIdx.x * blockDim.x + threadIdx.x;
    if (i < E) {
        int pos = atomicAdd(&cursor[dst[i]], 1);
        eid[pos] = i;
    }
}

// ------------------------- GCN gather (warp per destination node) -------------------------
// out[d,:] = dinv[d]^2 * h[d,:] + sum_in-edges dinv[s]*w*dinv[d] * h[s,:]
__global__ void k_gcn_gather(const float* __restrict__ h, const int* __restrict__ src,
                             const float* __restrict__ ew, const float* __restrict__ dinv,
                             const int* __restrict__ offs, const int* __restrict__ eid,
                             float* __restrict__ out, int n) {
    int t = blockIdx.x * blockDim.x + threadIdx.x;
    int d = t >> 5, lane = t & 31;
    if (d >= n) return;
    float dv = dinv[d];
    float4 acc = ((const float4*)(h + (size_t)d * FD))[lane];
    float c0 = dv * dv;
    acc.x *= c0; acc.y *= c0; acc.z *= c0; acc.w *= c0;
    int b = offs[d], e_end = offs[d + 1];
    for (int i = b; i < e_end; ++i) {
        int e = eid[i];
        int s = src[e];
        float c = dinv[s] * ew[e] * dv;
        float4 v = ((const float4*)(h + (size_t)s * FD))[lane];
        acc.x += c * v.x; acc.y += c * v.y; acc.z += c * v.z; acc.w += c * v.w;
    }
    ((float4*)(out + (size_t)d * FD))[lane] = acc;
}

// ------------------------- GAT -------------------------
// one warp per (node, head): asum/dsum dot products
__global__ void k_gat_node(const float* __restrict__ h, const float* __restrict__ as_,
                           const float* __restrict__ ad_, float* asum, float* dsum,
                           int nH, int H) {
    int t = blockIdx.x * blockDim.x + threadIdx.x;
    int w = t >> 5, lane = t & 31;
    if (w >= nH) return;
    int hd = w % H;
    float4 hv = ((const float4*)h)[(size_t)w * 32 + lane];
    float4 sv = ((const float4*)as_)[hd * 32 + lane];
    float4 dv = ((const float4*)ad_)[hd * 32 + lane];
    float a = hv.x * sv.x + hv.y * sv.y + hv.z * sv.z + hv.w * sv.w;
    float b = hv.x * dv.x + hv.y * dv.y + hv.z * dv.z + hv.w * dv.w;
    a = warp_sum(a);
    b = warp_sum(b);
    if (!lane) { asum[w] = a; dsum[w] = b; }
}

// alpha + leaky_relu, atomic segment max over destination. edges [0,E) real, [E,E+n) self-loops
__global__ void k_gat_alpha(const int* __restrict__ src, const int* __restrict__ dst,
                            const float* __restrict__ ew, const float* __restrict__ scal,
                            const float* __restrict__ cvec, const float* __restrict__ asum,
                            const float* __restrict__ dsum, float* __restrict__ alpha,
                            float* __restrict__ m, int E, int n, int H) {
    int idx = blockIdx.x * blockDim.x + threadIdx.x;
    if (idx >= (E + n) * H) return;
    int e = idx / H, hd = idx - e * H;
    int s, d;
    if (e < E) { s = src[e]; d = dst[e]; } else { s = e - E; d = s; }
    float a = asum[s * H + hd] + dsum[d * H + hd];
    if (cvec) {
        float ea = (e < E) ? ew[e] : scal[1];
        a += ea * cvec[hd];
    }
    a = a > 0.f ? a : 0.2f * a;   // leaky_relu 0.2
    alpha[idx] = a;
    atomic_max_f(&m[d * H + hd], a);
}

__global__ void k_gat_exp(const int* __restrict__ dst, float* __restrict__ alpha,
                          const float* __restrict__ m, float* __restrict__ den,
                          int E, int n, int H) {
    int idx = blockIdx.x * blockDim.x + threadIdx.x;
    if (idx >= (E + n) * H) return;
    int e = idx / H, hd = idx - e * H;
    int d = (e < E) ? dst[e] : (e - E);
    float p = __expf(alpha[idx] - m[d * H + hd]);
    alpha[idx] = p;
    atomicAdd(&den[d * H + hd], p);
}

// warp per destination node; accumulates ALL heads into one float4/lane
// (mean over heads shares the feature index), writes out row once.
template <int H>
__global__ void k_gat_gather(const float* __restrict__ h, const int* __restrict__ src,
                             const float* __restrict__ alpha, const float* __restrict__ den,
                             const int* __restrict__ offs, const int* __restrict__ eid,
                             float* __restrict__ out, int n, int E) {
    int t = blockIdx.x * blockDim.x + threadIdx.x;
    int d = t >> 5, lane = t & 31;
    if (d >= n) return;
    float rden[H];
#pragma unroll
    for (int hd = 0; hd < H; hd++) rden[hd] = 1.f / den[d * H + hd];
    float4 acc = make_float4(0.f, 0.f, 0.f, 0.f);
#pragma unroll
    for (int hd = 0; hd < H; hd++) {   // self-loop term
        float c = alpha[(size_t)(E + d) * H + hd] * rden[hd];
        float4 v = ((const float4*)(h + ((size_t)d * H + hd) * FD))[lane];
        acc.x += c * v.x; acc.y += c * v.y; acc.z += c * v.z; acc.w += c * v.w;
    }
    int b = offs[d], e_end = offs[d + 1];
    for (int i = b; i < e_end; ++i) {
        int e = eid[i];
        int s = src[e];
#pragma unroll
        for (int hd = 0; hd < H; hd++) {
            float c = alpha[(size_t)e * H + hd] * rden[hd];
            float4 v = ((const float4*)(h + ((size_t)s * H + hd) * FD))[lane];
            acc.x += c * v.x; acc.y += c * v.y; acc.z += c * v.z; acc.w += c * v.w;
        }
    }
    const float invH = 1.f / (float)H;
    acc.x *= invH; acc.y *= invH; acc.z *= invH; acc.w *= invH;
    ((float4*)(out + (size_t)d * FD))[lane] = acc;
}

// l = relu((gcn + bg + gat + ba)/2)
__global__ void k_combine(const float* __restrict__ gcn, const float* __restrict__ gat,
                          const float* __restrict__ bg, const float* __restrict__ ba,
                          float* __restrict__ o, long n128) {
    long i = (long)blockIdx.x * blockDim.x + threadIdx.x;
    if (i < n128) {
        int f = (int)(i & (FD - 1));
        float v = (gcn[i] + bg[f] + gat[i] + ba[f]) * 0.5f;
        o[i] = v > 0.f ? v : 0.f;
    }
}

// cat[n, 0:128]=a row, cat[n, 128:256]=b row
__global__ void k_cat(const float* __restrict__ a, const float* __restrict__ b,
                      float* __restrict__ o, long n256) {
    long i = (long)blockIdx.x * blockDim.x + threadIdx.x;
    if (i < n256) {
        long node = i >> 8;
        int f = (int)(i & 255);
        o[i] = (f < FD) ? a[node * FD + f] : b[node * FD + (f - FD)];
    }
}

// ------------------------- tiled SGEMM (double-buffered, fp32) -------------------------
// C[M,N] = A[M,K] @ op(B) (+bias[n]); TB=0: B is [K,N] row-major; TB=1: B is [N,K] row-major.
template <bool TB>
__global__ __launch_bounds__(256, 2) void k_sgemm(const float* __restrict__ A,
                                                  const float* __restrict__ B,
                                                  float* __restrict__ C, int M, int N, int K,
                                                  const float* __restrict__ bias) {
    __shared__ float As[2][16][128];
    __shared__ float Bs[2][16][128];
    const int m0 = blockIdx.y * 128;
    const int n0 = blockIdx.x * 128;
    const int tid = threadIdx.x;
    const int tx = tid & 15, ty = tid >> 4;
    const int rA = tid >> 2;          // 0..63
    const int kq = (tid & 3) << 2;    // 0,4,8,12
    const int kr = tid >> 5;          // 0..7   (TB=false B path)
    const int c4 = (tid & 31) << 2;   // 0..124 (TB=false B path)
    float acc[8][8] = {};
    float4 va[2], vb[2];

    auto load_tile = [&](int k0) {
#pragma unroll
        for (int hh = 0; hh < 2; hh++) {
            int gm = m0 + rA + hh * 64;
            va[hh] = make_float4(0.f, 0.f, 0.f, 0.f);
            if (gm < M) va[hh] = *(const float4*)(A + (size_t)gm * K + k0 + kq);
        }
        if (TB) {
#pragma unroll
            for (int hh = 0; hh < 2; hh++) {
                int gn = n0 + rA + hh * 64;
                vb[hh] = make_float4(0.f, 0.f, 0.f, 0.f);
                if (gn < N) vb[hh] = *(const float4*)(B + (size_t)gn * K + k0 + kq);
            }
        } else {
#pragma unroll
            for (int hh = 0; hh < 2; hh++) {
                int kk = kr + hh * 8;
                int gn = n0 + c4;
                float4 v = make_float4(0.f, 0.f, 0.f, 0.f);
                if (gn + 3 < N) {
                    v = *(const float4*)(B + (size_t)(k0 + kk) * N + gn);
                } else {
                    if (gn + 0 < N) v.x = B[(size_t)(k0 + kk) * N + gn + 0];
                    if (gn + 1 < N) v.y = B[(size_t)(k0 + kk) * N + gn + 1];
                    if (gn + 2 < N) v.z = B[(size_t)(k0 + kk) * N + gn + 2];
                    if (gn + 3 < N) v.w = B[(size_t)(k0 + kk) * N + gn + 3];
                }
                vb[hh] = v;
            }
        }
    };
    auto store_tile = [&](int buf) {
#pragma unroll
        for (int hh = 0; hh < 2; hh++) {
            int mm = rA + hh * 64;
            As[buf][kq + 0][mm] = va[hh].x; As[buf][kq + 1][mm] = va[hh].y;
            As[buf][kq + 2][mm] = va[hh].z; As[buf][kq + 3][mm] = va[hh].w;
        }
        if (TB) {
#pragma unroll
            for (int hh = 0; hh < 2; hh++) {
                int nn = rA + hh * 64;
                Bs[buf][kq + 0][nn] = vb[hh].x; Bs[buf][kq + 1][nn] = vb[hh].y;
                Bs[buf][kq + 2][nn] = vb[hh].z; Bs[buf][kq + 3][nn] = vb[hh].w;
            }
        } else {
#pragma unroll
            for (int hh = 0; hh < 2; hh++) {
                int kk = kr + hh * 8;
                Bs[buf][kk][c4 + 0] = vb[hh].x; Bs[buf][kk][c4 + 1] = vb[hh].y;
                Bs[buf][kk][c4 + 2] = vb[hh].z; Bs[buf][kk][c4 + 3] = vb[hh].w;
            }
        }
    };

    const int nk = K >> 4;
    load_tile(0);
    int buf = 0;
    for (int it = 0; it < nk; ++it) {
        store_tile(buf);
        __syncthreads();
        if (it + 1 < nk) load_tile((it + 1) << 4);   // overlap next global load with compute
#pragma unroll
        for (int k = 0; k < 16; k++) {
            float a[8], b[8];
            *(float4*)(a)     = *(const float4*)(&As[buf][k][ty * 8]);
            *(float4*)(a + 4) = *(const float4*)(&As[buf][k][ty * 8 + 4]);
            *(float4*)(b)     = *(const float4*)(&Bs[buf][k][tx * 8]);
            *(float4*)(b + 4) = *(const float4*)(&Bs[buf][k][tx * 8 + 4]);
#pragma unroll
            for (int i = 0; i < 8; i++)
#pragma unroll
                for (int j = 0; j < 8; j++)
                    acc[i][j] += a[i] * b[j];
        }
        buf ^= 1;
        // next iteration writes the OTHER buffer; per-iteration barrier bounds skew.
    }
#pragma unroll
    for (int i = 0; i < 8; i++) {
        int gm = m0 + ty * 8 + i;
        if (gm >= M) continue;
#pragma unroll
        for (int j = 0; j < 8; j += 4) {
            int gn = n0 + tx * 8 + j;
            if (gn + 3 < N) {
                float4 v = make_float4(acc[i][j], acc[i][j + 1], acc[i][j + 2], acc[i][j + 3]);
                if (bias) { v.x += bias[gn]; v.y += bias[gn + 1]; v.z += bias[gn + 2]; v.w += bias[gn + 3]; }
                *(float4*)(C + (size_t)gm * N + gn) = v;
            } else {
                for (int q = 0; q < 4; q++) {
                    int g = gn + q;
                    if (g < N) {
                        float v = acc[i][j + q];
                        if (bias) v += bias[g];
                        C[(size_t)gm * N + g] = v;
                    }
                }
            }
        }
    }
}

// ------------------------- TF32 tensor-core NT GEMM -------------------------
// C[M,N] = A[M,K] @ B[N,K]^T via mma.sync m16n8k8 tf32. K % 32 == 0.
// 256 threads = 8 warps (2 x 4), warp tile 64x32, CTA tile 128x128, BK=32.
#define TPAD 133   // 133 % 32 = 5; stores hit distinct banks (5*kq mod 32 spans all residues)
__global__ __launch_bounds__(256, 2) void k_tgemm_nt(const float* __restrict__ A,
                                                     const float* __restrict__ B,
                                                     float* __restrict__ C,
                                                     int M, int N, int K) {
    __shared__ unsigned As[32][TPAD];   // [k][m], tf32 bits
    __shared__ unsigned Bs[32][TPAD];   // [k][n], tf32 bits
    const int m0 = blockIdx.y * 128;
    const int n0 = blockIdx.x * 128;
    const int tid = threadIdx.x;
    const int wid = tid >> 5, lane = tid & 31;
    const int wm = wid >> 2, wn = wid & 3;          // 2 x 4 warp grid
    const int gid = lane >> 2, tig = lane & 3;      // mma fragment coords
    const int mwb = wm * 64, nwb = wn * 32;
    const int r = tid >> 3;                         // 0..31 (row within 32-row group)
    const int kq = (tid & 7) << 2;                  // 0,4,...,28

    float c[4][4][4] = {};                          // [m-tile][n-tile][reg]

    for (int k0 = 0; k0 < K; k0 += 32) {
        __syncthreads();                            // protect prior compute reads
#pragma unroll
        for (int rr = 0; rr < 4; rr++) {
            int row = r + rr * 32;
            int gm = m0 + row;
            float4 v = make_float4(0.f, 0.f, 0.f, 0.f);
            if (gm < M) v = *(const float4*)(A + (size_t)gm * K + k0 + kq);
            As[kq + 0][row] = f2tf32(v.x); As[kq + 1][row] = f2tf32(v.y);
            As[kq + 2][row] = f2tf32(v.z); As[kq + 3][row] = f2tf32(v.w);
            int gn = n0 + row;
            float4 w = make_float4(0.f, 0.f, 0.f, 0.f);
            if (gn < N) w = *(const float4*)(B + (size_t)gn * K + k0 + kq);
            Bs[kq + 0][row] = f2tf32(w.x); Bs[kq + 1][row] = f2tf32(w.y);
            Bs[kq + 2][row] = f2tf32(w.z); Bs[kq + 3][row] = f2tf32(w.w);
        }
        __syncthreads();
#pragma unroll
        for (int ks = 0; ks < 32; ks += 8) {
            unsigned af[4][4], bf[4][2];
#pragma unroll
            for (int mt = 0; mt < 4; mt++) {
                int mb = mwb + mt * 16 + gid;
                af[mt][0] = As[ks + tig][mb];
                af[mt][1] = As[ks + tig][mb + 8];
                af[mt][2] = As[ks + tig + 4][mb];
                af[mt][3] = As[ks + tig + 4][mb + 8];
            }
#pragma unroll
            for (int nt = 0; nt < 4; nt++) {
                int nb = nwb + nt * 8 + gid;
                bf[nt][0] = Bs[ks + tig][nb];
                bf[nt][1] = Bs[ks + tig + 4][nb];
            }
#pragma unroll
            for (int mt = 0; mt < 4; mt++)
#pragma unroll
                for (int nt = 0; nt < 4; nt++)
                    mma_tf32(c[mt][nt], af[mt][0], af[mt][1], af[mt][2], af[mt][3],
                             bf[nt][0], bf[nt][1]);
        }
    }
#pragma unroll
    for (int mt = 0; mt < 4; mt++) {
        int gm0 = m0 + mwb + mt * 16 + gid;
#pragma unroll
        for (int nt = 0; nt < 4; nt++) {
            int gn = n0 + nwb + nt * 8 + 2 * tig;
            if (gn < N) {   // gn even & N even -> gn+1 < N too
                if (gm0 < M)
                    *(float2*)(C + (size_t)gm0 * N + gn) = make_float2(c[mt][nt][0], c[mt][nt][1]);
                if (gm0 + 8 < M)
                    *(float2*)(C + (size_t)(gm0 + 8) * N + gn) = make_float2(c[mt][nt][2], c[mt][nt][3]);
            }
        }
    }
}

// ------------------------- host orchestration -------------------------
static inline unsigned gb(long n, int t) { return (unsigned)((n + t - 1) / t); }

extern "C" void kernel_launch(void* const* d_in, const int* in_sizes, int n_in,
                              void* d_out, int out_size) {
    (void)in_sizes; (void)n_in; (void)out_size;
    const float* x_drug = (const float*)d_in[0];
    const float* x_cir  = (const float*)d_in[1];
    const int*   dei    = (const int*)d_in[2];
    const int*   cei    = (const int*)d_in[3];
    const float* dew    = (const float*)d_in[4];
    const float* cew    = (const float*)d_in[5];
    const float* Wg1_d = (const float*)d_in[6];  const float* bg1_d = (const float*)d_in[7];
    const float* Wg2_d = (const float*)d_in[8];  const float* bg2_d = (const float*)d_in[9];
    const float* Wa_d  = (const float*)d_in[10]; const float* as_d  = (const float*)d_in[11];
    const float* ad_d  = (const float*)d_in[12]; const float* We_d  = (const float*)d_in[13];
    const float* ae_d  = (const float*)d_in[14]; const float* ba_d  = (const float*)d_in[15];
    const float* Wg1_c = (const float*)d_in[16]; const float* bg1_c = (const float*)d_in[17];
    const float* Wg2_c = (const float*)d_in[18]; const float* bg2_c = (const float*)d_in[19];
    const float* Wa_c  = (const float*)d_in[20]; const float* as_c  = (const float*)d_in[21];
    const float* ad_c  = (const float*)d_in[22]; const float* ba_c  = (const float*)d_in[23];
    const float* Kd    = (const float*)d_in[24]; const float* bKd   = (const float*)d_in[25];
    const float* Kc    = (const float*)d_in[26]; const float* bKc   = (const float*)d_in[27];
    float* out = (float*)d_out;

    const int* src_d = dei;       const int* dst_d = dei + ED_;
    const int* src_c = cei;       const int* dst_c = cei + EC_;

    float *p_h, *p_gcn, *p_gat, *p_deg, *p_dinv_d, *p_dinv_c, *p_asum, *p_dsum;
    float *p_m, *p_den, *p_alpha, *p_scal, *p_cvec;
    float *p_l1d, *p_l2d, *p_l1c, *p_l2c, *p_cat, *p_dfea, *p_cfea;
    int *p_cnt, *p_offs, *p_cursor, *p_eid_d, *p_eid_c;
    cudaGetSymbolAddress((void**)&p_h, g_h);
    cudaGetSymbolAddress((void**)&p_gcn, g_gcn);
    cudaGetSymbolAddress((void**)&p_gat, g_gat);
    cudaGetSymbolAddress((void**)&p_deg, g_deg);
    cudaGetSymbolAddress((void**)&p_dinv_d, g_dinv_d);
    cudaGetSymbolAddress((void**)&p_dinv_c, g_dinv_c);
    cudaGetSymbolAddress((void**)&p_asum, g_asum);
    cudaGetSymbolAddress((void**)&p_dsum, g_dsum);
    cudaGetSymbolAddress((void**)&p_m, g_m);
    cudaGetSymbolAddress((void**)&p_den, g_den);
    cudaGetSymbolAddress((void**)&p_alpha, g_alpha);
    cudaGetSymbolAddress((void**)&p_scal, g_scal);
    cudaGetSymbolAddress((void**)&p_cvec, g_cvec);
    cudaGetSymbolAddress((void**)&p_l1d, g_l1d);
    cudaGetSymbolAddress((void**)&p_l2d, g_l2d);
    cudaGetSymbolAddress((void**)&p_l1c, g_l1c);
    cudaGetSymbolAddress((void**)&p_l2c, g_l2c);
    cudaGetSymbolAddress((void**)&p_cat, g_cat);
    cudaGetSymbolAddress((void**)&p_dfea, g_dfea);
    cudaGetSymbolAddress((void**)&p_cfea, g_cfea);
    cudaGetSymbolAddress((void**)&p_cnt, g_cnt);
    cudaGetSymbolAddress((void**)&p_offs, g_offs);
    cudaGetSymbolAddress((void**)&p_cursor, g_cursor);
    cudaGetSymbolAddress((void**)&p_eid_d, g_eid_d);
    cudaGetSymbolAddress((void**)&p_eid_c, g_eid_c);

    auto fill = [](float* p, float v, long n) {
        k_fill<<<gb(n, 256), 256>>>(p, v, n);
    };
    auto gemm_nn = [](const float* A, const float* B, float* C, int M, int N, int K,
                      const float* bias) {
        dim3 grid((N + 127) / 128, (M + 127) / 128);
        k_sgemm<false><<<grid, 256>>>(A, B, C, M, N, K, bias);
    };
    auto build_csr = [&](const int* dst, int E, int n, int* eid) {
        k_ifill<<<gb(n, 256), 256>>>(p_cnt, 0, n);
        k_hist<<<gb(E, 256), 256>>>(dst, p_cnt, E);
        k_scan<<<1, 1024>>>(p_cnt, p_offs, p_cursor, n);
        k_place<<<gb(E, 256), 256>>>(dst, p_cursor, eid, E);
    };

    auto run_gcn = [&](const float* x, const float* Wg, const int* src,
                       const float* ew, const float* dinv, const int* eid,
                       float* outb, int n) {
        gemm_nn(x, Wg, p_h, n, FD, FD, nullptr);
        k_gcn_gather<<<gb((long)n * 32, 256), 256>>>(p_h, src, ew, dinv, p_offs, eid, outb, n);
    };

    auto run_gat = [&](const float* x, const float* Wa, const float* as_, const float* ad_,
                       const int* src, const int* dst, const float* ew, bool edge_attr,
                       const int* eid, float* outb, int n, int E, int H) {
        gemm_nn(x, Wa, p_h, n, H * FD, FD, nullptr);
        int nH = n * H;
        k_gat_node<<<gb((long)nH * 32, 256), 256>>>(p_h, as_, ad_, p_asum, p_dsum, nH, H);
        fill(p_m, -INFINITY, nH);
        fill(p_den, 0.f, nH);
        long tot = (long)(E + n) * H;
        k_gat_alpha<<<gb(tot, 256), 256>>>(src, dst, ew, p_scal, edge_attr ? p_cvec : nullptr,
                                           p_asum, p_dsum, p_alpha, p_m, E, n, H);
        k_gat_exp<<<gb(tot, 256), 256>>>(dst, p_alpha, p_m, p_den, E, n, H);
        if (H == 4)
            k_gat_gather<4><<<gb((long)n * 32, 256), 256>>>(p_h, src, p_alpha, p_den,
                                                            p_offs, eid, outb, n, E);
        else
            k_gat_gather<1><<<gb((long)n * 32, 256), 256>>>(p_h, src, p_alpha, p_den,
                                                            p_offs, eid, outb, n, E);
    };

    auto combine = [&](const float* bg, const float* ba, float* l, int n) {
        long n128 = (long)n * FD;
        k_combine<<<gb(n128, 256), 256>>>(p_gcn, p_gat, bg, ba, l, n128);
    };

    // ---- per-graph invariants: degree / symmetric-norm; edge-attn mean + coeffs ----
    fill(p_deg, 1.f, ND);                                    // self-loop weight 1
    k_deg<<<gb(ED_, 256), 256>>>(dst_d, dew, p_deg, ED_);
    k_dinv<<<gb(ND, 256), 256>>>(p_deg, p_dinv_d, ND);
    fill(p_deg, 1.f, NC);
    k_deg<<<gb(EC_, 256), 256>>>(dst_c, cew, p_deg, EC_);
    k_dinv<<<gb(NC, 256), 256>>>(p_deg, p_dinv_c, NC);
    fill(p_scal, 0.f, 2);
    k_sum<<<256, 256>>>(dew, p_scal, ED_);
    k_gat_prep<<<1, 128>>>(We_d, ae_d, p_scal, p_cvec, 1.f / (float)ED_);

    // ---- drug graph: CSR + 2 layers ----
    build_csr(dst_d, ED_, ND, p_eid_d);
    run_gcn(x_drug, Wg1_d, src_d, dew, p_dinv_d, p_eid_d, p_gcn, ND);
    run_gat(x_drug, Wa_d, as_d, ad_d, src_d, dst_d, dew, true, p_eid_d, p_gat, ND, ED_, NH);
    combine(bg1_d, ba_d, p_l1d, ND);
    run_gcn(p_l1d, Wg2_d, src_d, dew, p_dinv_d, p_eid_d, p_gcn, ND);
    run_gat(p_l1d, Wa_d, as_d, ad_d, src_d, dst_d, dew, true, p_eid_d, p_gat, ND, ED_, NH);
    combine(bg2_d, ba_d, p_l2d, ND);

    // ---- circ graph: CSR (offs rebuilt) + 2 layers ----
    build_csr(dst_c, EC_, NC, p_eid_c);
    run_gcn(x_cir, Wg1_c, src_c, cew, p_dinv_c, p_eid_c, p_gcn, NC);
    run_gat(x_cir, Wa_c, as_c, ad_c, src_c, dst_c, nullptr, false, p_eid_c, p_gat, NC, EC_, 1);
    combine(bg1_c, ba_c, p_l1c, NC);
    run_gcn(p_l1c, Wg2_c, src_c, cew, p_dinv_c, p_eid_c, p_gcn, NC);
    run_gat(p_l1c, Wa_c, as_c, ad_c, src_c, dst_c, nullptr, false, p_eid_c, p_gat, NC, EC_, 1);
    combine(bg2_c, ba_c, p_l2c, NC);

    // ---- CNN fuse: fea = [l1 | l2] @ Kflat^T + bK   (Kflat is [OC, 2F] row-major) ----
    k_cat<<<gb((long)ND * 256, 256), 256>>>(p_l1d, p_l2d, p_cat, (long)ND * 256);
    {
        dim3 grid((OCD + 127) / 128, (ND + 127) / 128);
        k_sgemm<true><<<grid, 256>>>(p_cat, Kd, p_dfea, ND, OCD, 2 * FD, bKd);
    }
    k_cat<<<gb((long)NC * 256, 256), 256>>>(p_l1c, p_l2c, p_cat, (long)NC * 256);
    {
        dim3 grid((OCD + 127) / 128, (NC + 127) / 128);
        k_sgemm<true><<<grid, 256>>>(p_cat, Kc, p_cfea, NC, OCD, 2 * FD, bKc);
    }

    // ---- final: out[0 : NC*ND] = cir_fea @ drug_fea^T (TF32 tensor cores) ----
    {
        dim3 grid((ND + 127) / 128, (NC + 127) / 128);
        k_tgemm_nt<<<grid, 256>>>(p_cfea, p_dfea, out, NC, ND, FD);
    }
    long tail = (long)ND * OCD;
    k_copy<<<gb(tail, 256), 256>>>(p_dfea, out + (size_t)NC * ND, tail);
}

// round 8
// speedup vs baseline: 1.6614x; 1.1142x over previous
#include <cuda_runtime.h>
#include <math.h>

#define ND 8000
#define NC 16000
#define FD 128
#define NH 4
#define OCD 128
#define ED_ 160000
#define EC_ 320000

// ------------------------- device scratch (no allocs allowed) -------------------------
__device__ __align__(16) float g_h[(size_t)ND * NH * FD];      // GEMM output h (max 8000x512)
__device__ __align__(16) float g_gcn[(size_t)NC * FD];
__device__ __align__(16) float g_gat[(size_t)NC * FD];
__device__ float g_deg[NC];
__device__ float g_dinv_d[ND];
__device__ float g_dinv_c[NC];
__device__ float g_asum[ND * NH];
__device__ float g_dsum[ND * NH];
__device__ float g_m[ND * NH];
__device__ float g_den[ND * NH];
__device__ float g_alpha[(ED_ + ND) * NH];
__device__ float g_scal[2];      // [0]=sum(ea), [1]=mean(ea)
__device__ float g_cvec[NH];     // per-head edge-attn coefficient
__device__ __align__(16) float g_l1d[(size_t)ND * FD];
__device__ __align__(16) float g_l2d[(size_t)ND * FD];
__device__ __align__(16) float g_l1c[(size_t)NC * FD];
__device__ __align__(16) float g_l2c[(size_t)NC * FD];
__device__ __align__(16) float g_cat[(size_t)NC * 2 * FD];
__device__ __align__(16) float g_dfea[(size_t)ND * OCD];
__device__ __align__(16) float g_cfea[(size_t)NC * OCD];
// CSR scratch (rebuilt per graph; offs/cnt/cursor shared since graphs processed sequentially)
__device__ int g_cnt[NC];
__device__ int g_offs[NC + 1];
__device__ int g_cursor[NC];
__device__ int g_eid_d[ED_];
__device__ int g_eid_c[EC_];

// ------------------------- helpers -------------------------
__device__ __forceinline__ float warp_sum(float v) {
#pragma unroll
    for (int o = 16; o; o >>= 1) v += __shfl_down_sync(0xffffffffu, v, o);
    return v;
}

// float atomic max via signed-max / unsigned-min bit tricks (correct incl. -inf init)
__device__ __forceinline__ void atomic_max_f(float* addr, float v) {
    if (v >= 0.f) atomicMax((int*)addr, __float_as_int(v));
    else          atomicMin((unsigned int*)addr, (unsigned int)__float_as_int(v));
}

__device__ __forceinline__ unsigned f2tf32(float x) {
    unsigned r;
    asm("cvt.rna.tf32.f32 %0, %1;" : "=r"(r) : "f"(x));
    return r;
}

__device__ __forceinline__ void mma_tf32(float* c, unsigned a0, unsigned a1, unsigned a2,
                                         unsigned a3, unsigned b0, unsigned b1) {
    asm volatile("mma.sync.aligned.m16n8k8.row.col.f32.tf32.tf32.f32 "
                 "{%0,%1,%2,%3}, {%4,%5,%6,%7}, {%8,%9}, {%0,%1,%2,%3};"
                 : "+f"(c[0]), "+f"(c[1]), "+f"(c[2]), "+f"(c[3])
                 : "r"(a0), "r"(a1), "r"(a2), "r"(a3), "r"(b0), "r"(b1));
}

// ------------------------- small utility kernels -------------------------
__global__ void k_fill(float* p, float v, long n) {
    long i = (long)blockIdx.x * blockDim.x + threadIdx.x;
    if (i < n) p[i] = v;
}

__global__ void k_ifill(int* p, int v, long n) {
    long i = (long)blockIdx.x * blockDim.x + threadIdx.x;
    if (i < n) p[i] = v;
}

__global__ void k_copy(const float* __restrict__ a, float* __restrict__ o, long n) {
    long i = (long)blockIdx.x * blockDim.x + threadIdx.x;
    if (i < n) o[i] = a[i];
}

__global__ void k_sum(const float* __restrict__ w, float* out, int n) {
    float s = 0.f;
    for (int i = blockIdx.x * blockDim.x + threadIdx.x; i < n; i += gridDim.x * blockDim.x)
        s += w[i];
    s = warp_sum(s);
    __shared__ float sh[8];
    int l = threadIdx.x & 31, wi = threadIdx.x >> 5;
    if (!l) sh[wi] = s;
    __syncthreads();
    if (threadIdx.x < 8) {
        float v = sh[threadIdx.x];
#pragma unroll
        for (int o = 4; o; o >>= 1) v += __shfl_down_sync(0xffu, v, o);
        if (!threadIdx.x) atomicAdd(out, v);
    }
}

// c[hd] = sum_f We[0,hd*F+f]*ae[hd,f];  scal[1] = scal[0]/E
__global__ void k_gat_prep(const float* __restrict__ We, const float* __restrict__ ae,
                           float* scal, float* cvec, float inv_e) {
    int wi = threadIdx.x >> 5, l = threadIdx.x & 31;
    if (wi < NH) {
        float4 a = ((const float4*)We)[wi * 32 + l];
        float4 b = ((const float4*)ae)[wi * 32 + l];
        float s = a.x * b.x + a.y * b.y + a.z * b.z + a.w * b.w;
        s = warp_sum(s);
        if (!l) cvec[wi] = s;
    }
    if (threadIdx.x == 0) scal[1] = scal[0] * inv_e;
}

__global__ void k_deg(const int* __restrict__ dst, const float* __restrict__ w, float* deg, int E) {
    int i = blockIdx.x * blockDim.x + threadIdx.x;
    if (i < E) atomicAdd(&deg[dst[i]], w[i]);
}

__global__ void k_dinv(const float* __restrict__ deg, float* dinv, int n) {
    int i = blockIdx.x * blockDim.x + threadIdx.x;
    if (i < n) { float d = deg[i]; dinv[i] = d > 0.f ? rsqrtf(d) : 0.f; }
}

// ------------------------- CSR build (per graph, by destination) -------------------------
__global__ void k_hist(const int* __restrict__ dst, int* __restrict__ cnt, int E) {
    int i = blockIdx.x * blockDim.x + threadIdx.x;
    if (i < E) atomicAdd(&cnt[dst[i]], 1);
}

// single-block exclusive scan over cnt[0..n) -> offs, cursor; offs[n] = total
__global__ void k_scan(const int* __restrict__ cnt, int* __restrict__ offs,
                       int* __restrict__ cursor, int n) {
    __shared__ int tmp[1024];
    __shared__ int carry_s;
    int tid = threadIdx.x;
    if (tid == 0) carry_s = 0;
    __syncthreads();
    for (int base = 0; base < n; base += 1024) {
        int v = (base + tid < n) ? cnt[base + tid] : 0;
        tmp[tid] = v;
        __syncthreads();
        int incl = v;
#pragma unroll
        for (int off = 1; off < 1024; off <<= 1) {
            int t = (tid >= off) ? tmp[tid - off] : 0;
            __syncthreads();
            tmp[tid] = incl = incl + t;
            __syncthreads();
        }
        int carry = carry_s;
        if (base + tid < n) {
            int ex = carry + incl - v;
            offs[base + tid] = ex;
            cursor[base + tid] = ex;
        }
        __syncthreads();
        if (tid == 1023) carry_s = carry + incl;  // lane 1023's incl = chunk total (zero-padded)
        __syncthreads();
    }
    if (tid == 0) offs[n] = carry_s;
}

__global__ void k_place(const int* __restrict__ dst, int* __restrict__ cursor,
                        int* __restrict__ eid, int E) {
    int i = blockIdx.x * blockDim.x + threadIdx.x;
    if (i < E) {
        int pos = atomicAdd(&cursor[dst[i]], 1);
        eid[pos] = i;
    }
}

// ------------------------- GCN gather (warp per destination node) -------------------------
// out[d,:] = dinv[d]^2 * h[d,:] + sum_in-edges dinv[s]*w*dinv[d] * h[s,:]
__global__ void k_gcn_gather(const float* __restrict__ h, const int* __restrict__ src,
                             const float* __restrict__ ew, const float* __restrict__ dinv,
                             const int* __restrict__ offs, const int* __restrict__ eid,
                             float* __restrict__ out, int n) {
    int t = blockIdx.x * blockDim.x + threadIdx.x;
    int d = t >> 5, lane = t & 31;
    if (d >= n) return;
    float dv = dinv[d];
    float4 acc = ((const float4*)(h + (size_t)d * FD))[lane];
    float c0 = dv * dv;
    acc.x *= c0; acc.y *= c0; acc.z *= c0; acc.w *= c0;
    int b = offs[d], e_end = offs[d + 1];
    for (int i = b; i < e_end; ++i) {
        int e = eid[i];
        int s = src[e];
        float c = dinv[s] * ew[e] * dv;
        float4 v = ((const float4*)(h + (size_t)s * FD))[lane];
        acc.x += c * v.x; acc.y += c * v.y; acc.z += c * v.z; acc.w += c * v.w;
    }
    ((float4*)(out + (size_t)d * FD))[lane] = acc;
}

// ------------------------- GAT -------------------------
// one warp per (node, head): asum/dsum dot products
__global__ void k_gat_node(const float* __restrict__ h, const float* __restrict__ as_,
                           const float* __restrict__ ad_, float* asum, float* dsum,
                           int nH, int H) {
    int t = blockIdx.x * blockDim.x + threadIdx.x;
    int w = t >> 5, lane = t & 31;
    if (w >= nH) return;
    int hd = w % H;
    float4 hv = ((const float4*)h)[(size_t)w * 32 + lane];
    float4 sv = ((const float4*)as_)[hd * 32 + lane];
    float4 dv = ((const float4*)ad_)[hd * 32 + lane];
    float a = hv.x * sv.x + hv.y * sv.y + hv.z * sv.z + hv.w * sv.w;
    float b = hv.x * dv.x + hv.y * dv.y + hv.z * dv.z + hv.w * dv.w;
    a = warp_sum(a);
    b = warp_sum(b);
    if (!lane) { asum[w] = a; dsum[w] = b; }
}

// alpha + leaky_relu, atomic segment max over destination. edges [0,E) real, [E,E+n) self-loops
__global__ void k_gat_alpha(const int* __restrict__ src, const int* __restrict__ dst,
                            const float* __restrict__ ew, const float* __restrict__ scal,
                            const float* __restrict__ cvec, const float* __restrict__ asum,
                            const float* __restrict__ dsum, float* __restrict__ alpha,
                            float* __restrict__ m, int E, int n, int H) {
    int idx = blockIdx.x * blockDim.x + threadIdx.x;
    if (idx >= (E + n) * H) return;
    int e = idx / H, hd = idx - e * H;
    int s, d;
    if (e < E) { s = src[e]; d = dst[e]; } else { s = e - E; d = s; }
    float a = asum[s * H + hd] + dsum[d * H + hd];
    if (cvec) {
        float ea = (e < E) ? ew[e] : scal[1];
        a += ea * cvec[hd];
    }
    a = a > 0.f ? a : 0.2f * a;   // leaky_relu 0.2
    alpha[idx] = a;
    atomic_max_f(&m[d * H + hd], a);
}

__global__ void k_gat_exp(const int* __restrict__ dst, float* __restrict__ alpha,
                          const float* __restrict__ m, float* __restrict__ den,
                          int E, int n, int H) {
    int idx = blockIdx.x * blockDim.x + threadIdx.x;
    if (idx >= (E + n) * H) return;
    int e = idx / H, hd = idx - e * H;
    int d = (e < E) ? dst[e] : (e - E);
    float p = __expf(alpha[idx] - m[d * H + hd]);
    alpha[idx] = p;
    atomicAdd(&den[d * H + hd], p);
}

// warp per destination node; accumulates ALL heads into one float4/lane
// (mean over heads shares the feature index), writes out row once.
template <int H>
__global__ void k_gat_gather(const float* __restrict__ h, const int* __restrict__ src,
                             const float* __restrict__ alpha, const float* __restrict__ den,
                             const int* __restrict__ offs, const int* __restrict__ eid,
                             float* __restrict__ out, int n, int E) {
    int t = blockIdx.x * blockDim.x + threadIdx.x;
    int d = t >> 5, lane = t & 31;
    if (d >= n) return;
    float rden[H];
#pragma unroll
    for (int hd = 0; hd < H; hd++) rden[hd] = 1.f / den[d * H + hd];
    float4 acc = make_float4(0.f, 0.f, 0.f, 0.f);
#pragma unroll
    for (int hd = 0; hd < H; hd++) {   // self-loop term
        float c = alpha[(size_t)(E + d) * H + hd] * rden[hd];
        float4 v = ((const float4*)(h + ((size_t)d * H + hd) * FD))[lane];
        acc.x += c * v.x; acc.y += c * v.y; acc.z += c * v.z; acc.w += c * v.w;
    }
    int b = offs[d], e_end = offs[d + 1];
    for (int i = b; i < e_end; ++i) {
        int e = eid[i];
        int s = src[e];
#pragma unroll
        for (int hd = 0; hd < H; hd++) {
            float c = alpha[(size_t)e * H + hd] * rden[hd];
            float4 v = ((const float4*)(h + ((size_t)s * H + hd) * FD))[lane];
            acc.x += c * v.x; acc.y += c * v.y; acc.z += c * v.z; acc.w += c * v.w;
        }
    }
    const float invH = 1.f / (float)H;
    acc.x *= invH; acc.y *= invH; acc.z *= invH; acc.w *= invH;
    ((float4*)(out + (size_t)d * FD))[lane] = acc;
}

// l = relu((gcn + bg + gat + ba)/2)
__global__ void k_combine(const float* __restrict__ gcn, const float* __restrict__ gat,
                          const float* __restrict__ bg, const float* __restrict__ ba,
                          float* __restrict__ o, long n128) {
    long i = (long)blockIdx.x * blockDim.x + threadIdx.x;
    if (i < n128) {
        int f = (int)(i & (FD - 1));
        float v = (gcn[i] + bg[f] + gat[i] + ba[f]) * 0.5f;
        o[i] = v > 0.f ? v : 0.f;
    }
}

// cat[n, 0:128]=a row, cat[n, 128:256]=b row
__global__ void k_cat(const float* __restrict__ a, const float* __restrict__ b,
                      float* __restrict__ o, long n256) {
    long i = (long)blockIdx.x * blockDim.x + threadIdx.x;
    if (i < n256) {
        long node = i >> 8;
        int f = (int)(i & 255);
        o[i] = (f < FD) ? a[node * FD + f] : b[node * FD + (f - FD)];
    }
}

// ------------------------- tiled SGEMM (double-buffered, fp32) -------------------------
// C[M,N] = A[M,K] @ op(B) (+bias[n]); TB=0: B is [K,N] row-major; TB=1: B is [N,K] row-major.
template <bool TB>
__global__ __launch_bounds__(256, 2) void k_sgemm(const float* __restrict__ A,
                                                  const float* __restrict__ B,
                                                  float* __restrict__ C, int M, int N, int K,
                                                  const float* __restrict__ bias) {
    __shared__ float As[2][16][128];
    __shared__ float Bs[2][16][128];
    const int m0 = blockIdx.y * 128;
    const int n0 = blockIdx.x * 128;
    const int tid = threadIdx.x;
    const int tx = tid & 15, ty = tid >> 4;
    const int rA = tid >> 2;          // 0..63
    const int kq = (tid & 3) << 2;    // 0,4,8,12
    const int kr = tid >> 5;          // 0..7   (TB=false B path)
    const int c4 = (tid & 31) << 2;   // 0..124 (TB=false B path)
    float acc[8][8] = {};
    float4 va[2], vb[2];

    auto load_tile = [&](int k0) {
#pragma unroll
        for (int hh = 0; hh < 2; hh++) {
            int gm = m0 + rA + hh * 64;
            va[hh] = make_float4(0.f, 0.f, 0.f, 0.f);
            if (gm < M) va[hh] = *(const float4*)(A + (size_t)gm * K + k0 + kq);
        }
        if (TB) {
#pragma unroll
            for (int hh = 0; hh < 2; hh++) {
                int gn = n0 + rA + hh * 64;
                vb[hh] = make_float4(0.f, 0.f, 0.f, 0.f);
                if (gn < N) vb[hh] = *(const float4*)(B + (size_t)gn * K + k0 + kq);
            }
        } else {
#pragma unroll
            for (int hh = 0; hh < 2; hh++) {
                int kk = kr + hh * 8;
                int gn = n0 + c4;
                float4 v = make_float4(0.f, 0.f, 0.f, 0.f);
                if (gn + 3 < N) {
                    v = *(const float4*)(B + (size_t)(k0 + kk) * N + gn);
                } else {
                    if (gn + 0 < N) v.x = B[(size_t)(k0 + kk) * N + gn + 0];
                    if (gn + 1 < N) v.y = B[(size_t)(k0 + kk) * N + gn + 1];
                    if (gn + 2 < N) v.z = B[(size_t)(k0 + kk) * N + gn + 2];
                    if (gn + 3 < N) v.w = B[(size_t)(k0 + kk) * N + gn + 3];
                }
                vb[hh] = v;
            }
        }
    };
    auto store_tile = [&](int buf) {
#pragma unroll
        for (int hh = 0; hh < 2; hh++) {
            int mm = rA + hh * 64;
            As[buf][kq + 0][mm] = va[hh].x; As[buf][kq + 1][mm] = va[hh].y;
            As[buf][kq + 2][mm] = va[hh].z; As[buf][kq + 3][mm] = va[hh].w;
        }
        if (TB) {
#pragma unroll
            for (int hh = 0; hh < 2; hh++) {
                int nn = rA + hh * 64;
                Bs[buf][kq + 0][nn] = vb[hh].x; Bs[buf][kq + 1][nn] = vb[hh].y;
                Bs[buf][kq + 2][nn] = vb[hh].z; Bs[buf][kq + 3][nn] = vb[hh].w;
            }
        } else {
#pragma unroll
            for (int hh = 0; hh < 2; hh++) {
                int kk = kr + hh * 8;
                Bs[buf][kk][c4 + 0] = vb[hh].x; Bs[buf][kk][c4 + 1] = vb[hh].y;
                Bs[buf][kk][c4 + 2] = vb[hh].z; Bs[buf][kk][c4 + 3] = vb[hh].w;
            }
        }
    };

    const int nk = K >> 4;
    load_tile(0);
    int buf = 0;
    for (int it = 0; it < nk; ++it) {
        store_tile(buf);
        __syncthreads();
        if (it + 1 < nk) load_tile((it + 1) << 4);   // overlap next global load with compute
#pragma unroll
        for (int k = 0; k < 16; k++) {
            float a[8], b[8];
            *(float4*)(a)     = *(const float4*)(&As[buf][k][ty * 8]);
            *(float4*)(a + 4) = *(const float4*)(&As[buf][k][ty * 8 + 4]);
            *(float4*)(b)     = *(const float4*)(&Bs[buf][k][tx * 8]);
            *(float4*)(b + 4) = *(const float4*)(&Bs[buf][k][tx * 8 + 4]);
#pragma unroll
            for (int i = 0; i < 8; i++)
#pragma unroll
                for (int j = 0; j < 8; j++)
                    acc[i][j] += a[i] * b[j];
        }
        buf ^= 1;
        // next iteration writes the OTHER buffer; per-iteration barrier bounds skew.
    }
#pragma unroll
    for (int i = 0; i < 8; i++) {
        int gm = m0 + ty * 8 + i;
        if (gm >= M) continue;
#pragma unroll
        for (int j = 0; j < 8; j += 4) {
            int gn = n0 + tx * 8 + j;
            if (gn + 3 < N) {
                float4 v = make_float4(acc[i][j], acc[i][j + 1], acc[i][j + 2], acc[i][j + 3]);
                if (bias) { v.x += bias[gn]; v.y += bias[gn + 1]; v.z += bias[gn + 2]; v.w += bias[gn + 3]; }
                *(float4*)(C + (size_t)gm * N + gn) = v;
            } else {
                for (int q = 0; q < 4; q++) {
                    int g = gn + q;
                    if (g < N) {
                        float v = acc[i][j + q];
                        if (bias) v += bias[g];
                        C[(size_t)gm * N + g] = v;
                    }
                }
            }
        }
    }
}

// ------------------------- TF32 tensor-core GEMM core -------------------------
// Shared compute core: As[k][m], Bs[k][n] tf32 tiles -> 128x128 C tile.
// 256 threads = 8 warps (2 x 4), warp tile 64x32, CTA tile 128x128, BK=32.
#define TPAD 133   // 133 % 32 = 5; stores hit distinct banks (5*kq mod 32 spans all residues)

// NT: C[M,N] = A[M,K] @ B[N,K]^T. K % 32 == 0.
__global__ __launch_bounds__(256, 2) void k_tgemm_nt(const float* __restrict__ A,
                                                     const float* __restrict__ B,
                                                     float* __restrict__ C,
                                                     int M, int N, int K) {
    __shared__ unsigned As[32][TPAD];   // [k][m], tf32 bits
    __shared__ unsigned Bs[32][TPAD];   // [k][n], tf32 bits
    const int m0 = blockIdx.y * 128;
    const int n0 = blockIdx.x * 128;
    const int tid = threadIdx.x;
    const int wid = tid >> 5, lane = tid & 31;
    const int wm = wid >> 2, wn = wid & 3;          // 2 x 4 warp grid
    const int gid = lane >> 2, tig = lane & 3;      // mma fragment coords
    const int mwb = wm * 64, nwb = wn * 32;
    const int r = tid >> 3;                         // 0..31 (row within 32-row group)
    const int kq = (tid & 7) << 2;                  // 0,4,...,28

    float c[4][4][4] = {};                          // [m-tile][n-tile][reg]

    for (int k0 = 0; k0 < K; k0 += 32) {
        __syncthreads();                            // protect prior compute reads
#pragma unroll
        for (int rr = 0; rr < 4; rr++) {
            int row = r + rr * 32;
            int gm = m0 + row;
            float4 v = make_float4(0.f, 0.f, 0.f, 0.f);
            if (gm < M) v = *(const float4*)(A + (size_t)gm * K + k0 + kq);
            As[kq + 0][row] = f2tf32(v.x); As[kq + 1][row] = f2tf32(v.y);
            As[kq + 2][row] = f2tf32(v.z); As[kq + 3][row] = f2tf32(v.w);
            int gn = n0 + row;
            float4 w = make_float4(0.f, 0.f, 0.f, 0.f);
            if (gn < N) w = *(const float4*)(B + (size_t)gn * K + k0 + kq);
            Bs[kq + 0][row] = f2tf32(w.x); Bs[kq + 1][row] = f2tf32(w.y);
            Bs[kq + 2][row] = f2tf32(w.z); Bs[kq + 3][row] = f2tf32(w.w);
        }
        __syncthreads();
#pragma unroll
        for (int ks = 0; ks < 32; ks += 8) {
            unsigned af[4][4], bf[4][2];
#pragma unroll
            for (int mt = 0; mt < 4; mt++) {
                int mb = mwb + mt * 16 + gid;
                af[mt][0] = As[ks + tig][mb];
                af[mt][1] = As[ks + tig][mb + 8];
                af[mt][2] = As[ks + tig + 4][mb];
                af[mt][3] = As[ks + tig + 4][mb + 8];
            }
#pragma unroll
            for (int nt = 0; nt < 4; nt++) {
                int nb = nwb + nt * 8 + gid;
                bf[nt][0] = Bs[ks + tig][nb];
                bf[nt][1] = Bs[ks + tig + 4][nb];
            }
#pragma unroll
            for (int mt = 0; mt < 4; mt++)
#pragma unroll
                for (int nt = 0; nt < 4; nt++)
                    mma_tf32(c[mt][nt], af[mt][0], af[mt][1], af[mt][2], af[mt][3],
                             bf[nt][0], bf[nt][1]);
        }
    }
#pragma unroll
    for (int mt = 0; mt < 4; mt++) {
        int gm0 = m0 + mwb + mt * 16 + gid;
#pragma unroll
        for (int nt = 0; nt < 4; nt++) {
            int gn = n0 + nwb + nt * 8 + 2 * tig;
            if (gn < N) {   // gn even & N even -> gn+1 < N too
                if (gm0 < M)
                    *(float2*)(C + (size_t)gm0 * N + gn) = make_float2(c[mt][nt][0], c[mt][nt][1]);
                if (gm0 + 8 < M)
                    *(float2*)(C + (size_t)(gm0 + 8) * N + gn) = make_float2(c[mt][nt][2], c[mt][nt][3]);
            }
        }
    }
}

// NN: C[M,N] = A[M,K] @ B[K,N], B row-major. K % 32 == 0, N % 4 == 0.
__global__ __launch_bounds__(256, 2) void k_tgemm_nn(const float* __restrict__ A,
                                                     const float* __restrict__ B,
                                                     float* __restrict__ C,
                                                     int M, int N, int K) {
    __shared__ unsigned As[32][TPAD];   // [k][m]
    __shared__ unsigned Bs[32][TPAD];   // [k][n]
    const int m0 = blockIdx.y * 128;
    const int n0 = blockIdx.x * 128;
    const int tid = threadIdx.x;
    const int wid = tid >> 5, lane = tid & 31;
    const int wm = wid >> 2, wn = wid & 3;
    const int gid = lane >> 2, tig = lane & 3;
    const int mwb = wm * 64, nwb = wn * 32;
    const int r = tid >> 3;                         // 0..31
    const int kq = (tid & 7) << 2;                  // 0,4,...,28 (A loader k-offset)

    float c[4][4][4] = {};

    for (int k0 = 0; k0 < K; k0 += 32) {
        __syncthreads();
        // A: 128 m-rows x 32 k (same as NT)
#pragma unroll
        for (int rr = 0; rr < 4; rr++) {
            int row = r + rr * 32;
            int gm = m0 + row;
            float4 v = make_float4(0.f, 0.f, 0.f, 0.f);
            if (gm < M) v = *(const float4*)(A + (size_t)gm * K + k0 + kq);
            As[kq + 0][row] = f2tf32(v.x); As[kq + 1][row] = f2tf32(v.y);
            As[kq + 2][row] = f2tf32(v.z); As[kq + 3][row] = f2tf32(v.w);
        }
        // B: 32 k-rows x 128 n; thread r owns k-row r, 4 float4s across n
#pragma unroll
        for (int i = 0; i < 4; i++) {
            int nn = ((tid & 7) + 8 * i) << 2;      // 0..124
            int gn = n0 + nn;
            float4 v = make_float4(0.f, 0.f, 0.f, 0.f);
            if (gn + 3 < N) v = *(const float4*)(B + (size_t)(k0 + r) * N + gn);
            Bs[r][nn + 0] = f2tf32(v.x); Bs[r][nn + 1] = f2tf32(v.y);
            Bs[r][nn + 2] = f2tf32(v.z); Bs[r][nn + 3] = f2tf32(v.w);
        }
        __syncthreads();
#pragma unroll
        for (int ks = 0; ks < 32; ks += 8) {
            unsigned af[4][4], bf[4][2];
#pragma unroll
            for (int mt = 0; mt < 4; mt++) {
                int mb = mwb + mt * 16 + gid;
                af[mt][0] = As[ks + tig][mb];
                af[mt][1] = As[ks + tig][mb + 8];
                af[mt][2] = As[ks + tig + 4][mb];
                af[mt][3] = As[ks + tig + 4][mb + 8];
            }
#pragma unroll
            for (int nt = 0; nt < 4; nt++) {
                int nb = nwb + nt * 8 + gid;
                bf[nt][0] = Bs[ks + tig][nb];
                bf[nt][1] = Bs[ks + tig + 4][nb];
            }
#pragma unroll
            for (int mt = 0; mt < 4; mt++)
#pragma unroll
                for (int nt = 0; nt < 4; nt++)
                    mma_tf32(c[mt][nt], af[mt][0], af[mt][1], af[mt][2], af[mt][3],
                             bf[nt][0], bf[nt][1]);
        }
    }
#pragma unroll
    for (int mt = 0; mt < 4; mt++) {
        int gm0 = m0 + mwb + mt * 16 + gid;
#pragma unroll
        for (int nt = 0; nt < 4; nt++) {
            int gn = n0 + nwb + nt * 8 + 2 * tig;
            if (gn + 1 < N) {
                if (gm0 < M)
                    *(float2*)(C + (size_t)gm0 * N + gn) = make_float2(c[mt][nt][0], c[mt][nt][1]);
                if (gm0 + 8 < M)
                    *(float2*)(C + (size_t)(gm0 + 8) * N + gn) = make_float2(c[mt][nt][2], c[mt][nt][3]);
            }
        }
    }
}

// ------------------------- host orchestration -------------------------
static inline unsigned gb(long n, int t) { return (unsigned)((n + t - 1) / t); }

extern "C" void kernel_launch(void* const* d_in, const int* in_sizes, int n_in,
                              void* d_out, int out_size) {
    (void)in_sizes; (void)n_in; (void)out_size;
    const float* x_drug = (const float*)d_in[0];
    const float* x_cir  = (const float*)d_in[1];
    const int*   dei    = (const int*)d_in[2];
    const int*   cei    = (const int*)d_in[3];
    const float* dew    = (const float*)d_in[4];
    const float* cew    = (const float*)d_in[5];
    const float* Wg1_d = (const float*)d_in[6];  const float* bg1_d = (const float*)d_in[7];
    const float* Wg2_d = (const float*)d_in[8];  const float* bg2_d = (const float*)d_in[9];
    const float* Wa_d  = (const float*)d_in[10]; const float* as_d  = (const float*)d_in[11];
    const float* ad_d  = (const float*)d_in[12]; const float* We_d  = (const float*)d_in[13];
    const float* ae_d  = (const float*)d_in[14]; const float* ba_d  = (const float*)d_in[15];
    const float* Wg1_c = (const float*)d_in[16]; const float* bg1_c = (const float*)d_in[17];
    const float* Wg2_c = (const float*)d_in[18]; const float* bg2_c = (const float*)d_in[19];
    const float* Wa_c  = (const float*)d_in[20]; const float* as_c  = (const float*)d_in[21];
    const float* ad_c  = (const float*)d_in[22]; const float* ba_c  = (const float*)d_in[23];
    const float* Kd    = (const float*)d_in[24]; const float* bKd   = (const float*)d_in[25];
    const float* Kc    = (const float*)d_in[26]; const float* bKc   = (const float*)d_in[27];
    float* out = (float*)d_out;

    const int* src_d = dei;       const int* dst_d = dei + ED_;
    const int* src_c = cei;       const int* dst_c = cei + EC_;

    float *p_h, *p_gcn, *p_gat, *p_deg, *p_dinv_d, *p_dinv_c, *p_asum, *p_dsum;
    float *p_m, *p_den, *p_alpha, *p_scal, *p_cvec;
    float *p_l1d, *p_l2d, *p_l1c, *p_l2c, *p_cat, *p_dfea, *p_cfea;
    int *p_cnt, *p_offs, *p_cursor, *p_eid_d, *p_eid_c;
    cudaGetSymbolAddress((void**)&p_h, g_h);
    cudaGetSymbolAddress((void**)&p_gcn, g_gcn);
    cudaGetSymbolAddress((void**)&p_gat, g_gat);
    cudaGetSymbolAddress((void**)&p_deg, g_deg);
    cudaGetSymbolAddress((void**)&p_dinv_d, g_dinv_d);
    cudaGetSymbolAddress((void**)&p_dinv_c, g_dinv_c);
    cudaGetSymbolAddress((void**)&p_asum, g_asum);
    cudaGetSymbolAddress((void**)&p_dsum, g_dsum);
    cudaGetSymbolAddress((void**)&p_m, g_m);
    cudaGetSymbolAddress((void**)&p_den, g_den);
    cudaGetSymbolAddress((void**)&p_alpha, g_alpha);
    cudaGetSymbolAddress((void**)&p_scal, g_scal);
    cudaGetSymbolAddress((void**)&p_cvec, g_cvec);
    cudaGetSymbolAddress((void**)&p_l1d, g_l1d);
    cudaGetSymbolAddress((void**)&p_l2d, g_l2d);
    cudaGetSymbolAddress((void**)&p_l1c, g_l1c);
    cudaGetSymbolAddress((void**)&p_l2c, g_l2c);
    cudaGetSymbolAddress((void**)&p_cat, g_cat);
    cudaGetSymbolAddress((void**)&p_dfea, g_dfea);
    cudaGetSymbolAddress((void**)&p_cfea, g_cfea);
    cudaGetSymbolAddress((void**)&p_cnt, g_cnt);
    cudaGetSymbolAddress((void**)&p_offs, g_offs);
    cudaGetSymbolAddress((void**)&p_cursor, g_cursor);
    cudaGetSymbolAddress((void**)&p_eid_d, g_eid_d);
    cudaGetSymbolAddress((void**)&p_eid_c, g_eid_c);

    auto fill = [](float* p, float v, long n) {
        k_fill<<<gb(n, 256), 256>>>(p, v, n);
    };
    auto tgemm_nn = [](const float* A, const float* B, float* C, int M, int N, int K) {
        dim3 grid((N + 127) / 128, (M + 127) / 128);
        k_tgemm_nn<<<grid, 256>>>(A, B, C, M, N, K);
    };
    auto build_csr = [&](const int* dst, int E, int n, int* eid) {
        k_ifill<<<gb(n, 256), 256>>>(p_cnt, 0, n);
        k_hist<<<gb(E, 256), 256>>>(dst, p_cnt, E);
        k_scan<<<1, 1024>>>(p_cnt, p_offs, p_cursor, n);
        k_place<<<gb(E, 256), 256>>>(dst, p_cursor, eid, E);
    };

    auto run_gcn = [&](const float* x, const float* Wg, const int* src,
                       const float* ew, const float* dinv, const int* eid,
                       float* outb, int n) {
        tgemm_nn(x, Wg, p_h, n, FD, FD);
        k_gcn_gather<<<gb((long)n * 32, 256), 256>>>(p_h, src, ew, dinv, p_offs, eid, outb, n);
    };

    auto run_gat = [&](const float* x, const float* Wa, const float* as_, const float* ad_,
                       const int* src, const int* dst, const float* ew, bool edge_attr,
                       const int* eid, float* outb, int n, int E, int H) {
        tgemm_nn(x, Wa, p_h, n, H * FD, FD);
        int nH = n * H;
        k_gat_node<<<gb((long)nH * 32, 256), 256>>>(p_h, as_, ad_, p_asum, p_dsum, nH, H);
        fill(p_m, -INFINITY, nH);
        fill(p_den, 0.f, nH);
        long tot = (long)(E + n) * H;
        k_gat_alpha<<<gb(tot, 256), 256>>>(src, dst, ew, p_scal, edge_attr ? p_cvec : nullptr,
                                           p_asum, p_dsum, p_alpha, p_m, E, n, H);
        k_gat_exp<<<gb(tot, 256), 256>>>(dst, p_alpha, p_m, p_den, E, n, H);
        if (H == 4)
            k_gat_gather<4><<<gb((long)n * 32, 256), 256>>>(p_h, src, p_alpha, p_den,
                                                            p_offs, eid, outb, n, E);
        else
            k_gat_gather<1><<<gb((long)n * 32, 256), 256>>>(p_h, src, p_alpha, p_den,
                                                            p_offs, eid, outb, n, E);
    };

    auto combine = [&](const float* bg, const float* ba, float* l, int n) {
        long n128 = (long)n * FD;
        k_combine<<<gb(n128, 256), 256>>>(p_gcn, p_gat, bg, ba, l, n128);
    };

    // ---- per-graph invariants: degree / symmetric-norm; edge-attn mean + coeffs ----
    fill(p_deg, 1.f, ND);                                    // self-loop weight 1
    k_deg<<<gb(ED_, 256), 256>>>(dst_d, dew, p_deg, ED_);
    k_dinv<<<gb(ND, 256), 256>>>(p_deg, p_dinv_d, ND);
    fill(p_deg, 1.f, NC);
    k_deg<<<gb(EC_, 256), 256>>>(dst_c, cew, p_deg, EC_);
    k_dinv<<<gb(NC, 256), 256>>>(p_deg, p_dinv_c, NC);
    fill(p_scal, 0.f, 2);
    k_sum<<<256, 256>>>(dew, p_scal, ED_);
    k_gat_prep<<<1, 128>>>(We_d, ae_d, p_scal, p_cvec, 1.f / (float)ED_);

    // ---- drug graph: CSR + 2 layers ----
    build_csr(dst_d, ED_, ND, p_eid_d);
    run_gcn(x_drug, Wg1_d, src_d, dew, p_dinv_d, p_eid_d, p_gcn, ND);
    run_gat(x_drug, Wa_d, as_d, ad_d, src_d, dst_d, dew, true, p_eid_d, p_gat, ND, ED_, NH);
    combine(bg1_d, ba_d, p_l1d, ND);
    run_gcn(p_l1d, Wg2_d, src_d, dew, p_dinv_d, p_eid_d, p_gcn, ND);
    run_gat(p_l1d, Wa_d, as_d, ad_d, src_d, dst_d, dew, true, p_eid_d, p_gat, ND, ED_, NH);
    combine(bg2_d, ba_d, p_l2d, ND);

    // ---- circ graph: CSR (offs rebuilt) + 2 layers ----
    build_csr(dst_c, EC_, NC, p_eid_c);
    run_gcn(x_cir, Wg1_c, src_c, cew, p_dinv_c, p_eid_c, p_gcn, NC);
    run_gat(x_cir, Wa_c, as_c, ad_c, src_c, dst_c, nullptr, false, p_eid_c, p_gat, NC, EC_, 1);
    combine(bg1_c, ba_c, p_l1c, NC);
    run_gcn(p_l1c, Wg2_c, src_c, cew, p_dinv_c, p_eid_c, p_gcn, NC);
    run_gat(p_l1c, Wa_c, as_c, ad_c, src_c, dst_c, nullptr, false, p_eid_c, p_gat, NC, EC_, 1);
    combine(bg2_c, ba_c, p_l2c, NC);

    // ---- CNN fuse: fea = [l1 | l2] @ Kflat^T + bK   (Kflat is [OC, 2F] row-major) ----
    k_cat<<<gb((long)ND * 256, 256), 256>>>(p_l1d, p_l2d, p_cat, (long)ND * 256);
    {
        dim3 grid((OCD + 127) / 128, (ND + 127) / 128);
        k_sgemm<true><<<grid, 256>>>(p_cat, Kd, p_dfea, ND, OCD, 2 * FD, bKd);
    }
    k_cat<<<gb((long)NC * 256, 256), 256>>>(p_l1c, p_l2c, p_cat, (long)NC * 256);
    {
        dim3 grid((OCD + 127) / 128, (NC + 127) / 128);
        k_sgemm<true><<<grid, 256>>>(p_cat, Kc, p_cfea, NC, OCD, 2 * FD, bKc);
    }

    // ---- final: out[0 : NC*ND] = cir_fea @ drug_fea^T (TF32 tensor cores) ----
    {
        dim3 grid((ND + 127) / 128, (NC + 127) / 128);
        k_tgemm_nt<<<grid, 256>>>(p_cfea, p_dfea, out, NC, ND, FD);
    }
    long tail = (long)ND * OCD;
    k_copy<<<gb(tail, 256), 256>>>(p_dfea, out + (size_t)NC * ND, tail);
}

// round 9
// speedup vs baseline: 1.6682x; 1.0041x over previous
#include <cuda_runtime.h>
#include <math.h>

#define ND 8000
#define NC 16000
#define FD 128
#define NH 4
#define OCD 128
#define ED_ 160000
#define EC_ 320000

// ------------------------- device scratch (no allocs allowed) -------------------------
__device__ __align__(16) float g_h[(size_t)ND * NH * FD];      // GEMM output h (max 8000x512)
__device__ __align__(16) float g_gcn[(size_t)NC * FD];
__device__ __align__(16) float g_gat[(size_t)NC * FD];
__device__ float g_deg[NC];
__device__ float g_dinv_d[ND];
__device__ float g_dinv_c[NC];
__device__ float g_asum[ND * NH];
__device__ float g_dsum[ND * NH];
__device__ float g_m[ND * NH];
__device__ float g_den[ND * NH];
__device__ float g_alpha[(ED_ + ND) * NH];
__device__ float g_scal[2];      // [0]=sum(ea), [1]=mean(ea)
__device__ float g_cvec[NH];     // per-head edge-attn coefficient
__device__ __align__(16) float g_l1d[(size_t)ND * FD];
__device__ __align__(16) float g_l2d[(size_t)ND * FD];
__device__ __align__(16) float g_l1c[(size_t)NC * FD];
__device__ __align__(16) float g_l2c[(size_t)NC * FD];
__device__ __align__(16) float g_cat[(size_t)NC * 2 * FD];
__device__ __align__(16) float g_dfea[(size_t)ND * OCD];
__device__ __align__(16) float g_cfea[(size_t)NC * OCD];
// CSR scratch (rebuilt per graph; offs/cnt/cursor shared since graphs processed sequentially)
__device__ int g_cnt[NC];
__device__ int g_offs[NC + 1];
__device__ int g_cursor[NC];
__device__ int g_eid_d[ED_];
__device__ int g_eid_c[EC_];

// ------------------------- helpers -------------------------
__device__ __forceinline__ float warp_sum(float v) {
#pragma unroll
    for (int o = 16; o; o >>= 1) v += __shfl_down_sync(0xffffffffu, v, o);
    return v;
}

// float atomic max via signed-max / unsigned-min bit tricks (correct incl. -inf init)
__device__ __forceinline__ void atomic_max_f(float* addr, float v) {
    if (v >= 0.f) atomicMax((int*)addr, __float_as_int(v));
    else          atomicMin((unsigned int*)addr, (unsigned int)__float_as_int(v));
}

__device__ __forceinline__ unsigned f2tf32(float x) {
    unsigned r;
    asm("cvt.rna.tf32.f32 %0, %1;" : "=r"(r) : "f"(x));
    return r;
}

__device__ __forceinline__ void mma_tf32(float* c, unsigned a0, unsigned a1, unsigned a2,
                                         unsigned a3, unsigned b0, unsigned b1) {
    asm volatile("mma.sync.aligned.m16n8k8.row.col.f32.tf32.tf32.f32 "
                 "{%0,%1,%2,%3}, {%4,%5,%6,%7}, {%8,%9}, {%0,%1,%2,%3};"
                 : "+f"(c[0]), "+f"(c[1]), "+f"(c[2]), "+f"(c[3])
                 : "r"(a0), "r"(a1), "r"(a2), "r"(a3), "r"(b0), "r"(b1));
}

// cp.async 16B global->shared; invalid -> zero-fill (src-size 0 reads nothing)
__device__ __forceinline__ void cp16(unsigned* smem_dst, const float* gsrc, bool valid) {
    unsigned sa = (unsigned)__cvta_generic_to_shared(smem_dst);
    int sz = valid ? 16 : 0;
    asm volatile("cp.async.ca.shared.global [%0], [%1], 16, %2;"
                 :: "r"(sa), "l"(gsrc), "r"(sz) : "memory");
}
#define CP_COMMIT() asm volatile("cp.async.commit_group;" ::: "memory")
#define CP_WAIT0()  asm volatile("cp.async.wait_group 0;" ::: "memory")
#define CP_WAIT1()  asm volatile("cp.async.wait_group 1;" ::: "memory")

// ------------------------- small utility kernels -------------------------
__global__ void k_fill(float* p, float v, long n) {
    long i = (long)blockIdx.x * blockDim.x + threadIdx.x;
    if (i < n) p[i] = v;
}

__global__ void k_ifill(int* p, int v, long n) {
    long i = (long)blockIdx.x * blockDim.x + threadIdx.x;
    if (i < n) p[i] = v;
}

__global__ void k_copy(const float* __restrict__ a, float* __restrict__ o, long n) {
    long i = (long)blockIdx.x * blockDim.x + threadIdx.x;
    if (i < n) o[i] = a[i];
}

__global__ void k_sum(const float* __restrict__ w, float* out, int n) {
    float s = 0.f;
    for (int i = blockIdx.x * blockDim.x + threadIdx.x; i < n; i += gridDim.x * blockDim.x)
        s += w[i];
    s = warp_sum(s);
    __shared__ float sh[8];
    int l = threadIdx.x & 31, wi = threadIdx.x >> 5;
    if (!l) sh[wi] = s;
    __syncthreads();
    if (threadIdx.x < 8) {
        float v = sh[threadIdx.x];
#pragma unroll
        for (int o = 4; o; o >>= 1) v += __shfl_down_sync(0xffu, v, o);
        if (!threadIdx.x) atomicAdd(out, v);
    }
}

// c[hd] = sum_f We[0,hd*F+f]*ae[hd,f];  scal[1] = scal[0]/E
__global__ void k_gat_prep(const float* __restrict__ We, const float* __restrict__ ae,
                           float* scal, float* cvec, float inv_e) {
    int wi = threadIdx.x >> 5, l = threadIdx.x & 31;
    if (wi < NH) {
        float4 a = ((const float4*)We)[wi * 32 + l];
        float4 b = ((const float4*)ae)[wi * 32 + l];
        float s = a.x * b.x + a.y * b.y + a.z * b.z + a.w * b.w;
        s = warp_sum(s);
        if (!l) cvec[wi] = s;
    }
    if (threadIdx.x == 0) scal[1] = scal[0] * inv_e;
}

__global__ void k_deg(const int* __restrict__ dst, const float* __restrict__ w, float* deg, int E) {
    int i = blockIdx.x * blockDim.x + threadIdx.x;
    if (i < E) atomicAdd(&deg[dst[i]], w[i]);
}

__global__ void k_dinv(const float* __restrict__ deg, float* dinv, int n) {
    int i = blockIdx.x * blockDim.x + threadIdx.x;
    if (i < n) { float d = deg[i]; dinv[i] = d > 0.f ? rsqrtf(d) : 0.f; }
}

// ------------------------- CSR build (per graph, by destination) -------------------------
__global__ void k_hist(const int* __restrict__ dst, int* __restrict__ cnt, int E) {
    int i = blockIdx.x * blockDim.x + threadIdx.x;
    if (i < E) atomicAdd(&cnt[dst[i]], 1);
}

// single-block exclusive scan over cnt[0..n) -> offs, cursor; offs[n] = total
__global__ void k_scan(const int* __restrict__ cnt, int* __restrict__ offs,
                       int* __restrict__ cursor, int n) {
    __shared__ int tmp[1024];
    __shared__ int carry_s;
    int tid = threadIdx.x;
    if (tid == 0) carry_s = 0;
    __syncthreads();
    for (int base = 0; base < n; base += 1024) {
        int v = (base + tid < n) ? cnt[base + tid] : 0;
        tmp[tid] = v;
        __syncthreads();
        int incl = v;
#pragma unroll
        for (int off = 1; off < 1024; off <<= 1) {
            int t = (tid >= off) ? tmp[tid - off] : 0;
            __syncthreads();
            tmp[tid] = incl = incl + t;
            __syncthreads();
        }
        int carry = carry_s;
        if (base + tid < n) {
            int ex = carry + incl - v;
            offs[base + tid] = ex;
            cursor[base + tid] = ex;
        }
        __syncthreads();
        if (tid == 1023) carry_s = carry + incl;  // lane 1023's incl = chunk total (zero-padded)
        __syncthreads();
    }
    if (tid == 0) offs[n] = carry_s;
}

__global__ void k_place(const int* __restrict__ dst, int* __restrict__ cursor,
                        int* __restrict__ eid, int E) {
    int i = blockIdx.x * blockDim.x + threadIdx.x;
    if (i < E) {
        int pos = atomicAdd(&cursor[dst[i]], 1);
        eid[pos] = i;
    }
}

// ------------------------- GCN gather (warp per destination node) -------------------------
// out[d,:] = dinv[d]^2 * h[d,:] + sum_in-edges dinv[s]*w*dinv[d] * h[s,:]
__global__ void k_gcn_gather(const float* __restrict__ h, const int* __restrict__ src,
                             const float* __restrict__ ew, const float* __restrict__ dinv,
                             const int* __restrict__ offs, const int* __restrict__ eid,
                             float* __restrict__ out, int n) {
    int t = blockIdx.x * blockDim.x + threadIdx.x;
    int d = t >> 5, lane = t & 31;
    if (d >= n) return;
    float dv = dinv[d];
    float4 acc = ((const float4*)(h + (size_t)d * FD))[lane];
    float c0 = dv * dv;
    acc.x *= c0; acc.y *= c0; acc.z *= c0; acc.w *= c0;
    int b = offs[d], e_end = offs[d + 1];
    for (int i = b; i < e_end; ++i) {
        int e = eid[i];
        int s = src[e];
        float c = dinv[s] * ew[e] * dv;
        float4 v = ((const float4*)(h + (size_t)s * FD))[lane];
        acc.x += c * v.x; acc.y += c * v.y; acc.z += c * v.z; acc.w += c * v.w;
    }
    ((float4*)(out + (size_t)d * FD))[lane] = acc;
}

// ------------------------- GAT -------------------------
// one warp per (node, head): asum/dsum dot products
__global__ void k_gat_node(const float* __restrict__ h, const float* __restrict__ as_,
                           const float* __restrict__ ad_, float* asum, float* dsum,
                           int nH, int H) {
    int t = blockIdx.x * blockDim.x + threadIdx.x;
    int w = t >> 5, lane = t & 31;
    if (w >= nH) return;
    int hd = w % H;
    float4 hv = ((const float4*)h)[(size_t)w * 32 + lane];
    float4 sv = ((const float4*)as_)[hd * 32 + lane];
    float4 dv = ((const float4*)ad_)[hd * 32 + lane];
    float a = hv.x * sv.x + hv.y * sv.y + hv.z * sv.z + hv.w * sv.w;
    float b = hv.x * dv.x + hv.y * dv.y + hv.z * dv.z + hv.w * dv.w;
    a = warp_sum(a);
    b = warp_sum(b);
    if (!lane) { asum[w] = a; dsum[w] = b; }
}

// alpha + leaky_relu, atomic segment max over destination. edges [0,E) real, [E,E+n) self-loops
__global__ void k_gat_alpha(const int* __restrict__ src, const int* __restrict__ dst,
                            const float* __restrict__ ew, const float* __restrict__ scal,
                            const float* __restrict__ cvec, const float* __restrict__ asum,
                            const float* __restrict__ dsum, float* __restrict__ alpha,
                            float* __restrict__ m, int E, int n, int H) {
    int idx = blockIdx.x * blockDim.x + threadIdx.x;
    if (idx >= (E + n) * H) return;
    int e = idx / H, hd = idx - e * H;
    int s, d;
    if (e < E) { s = src[e]; d = dst[e]; } else { s = e - E; d = s; }
    float a = asum[s * H + hd] + dsum[d * H + hd];
    if (cvec) {
        float ea = (e < E) ? ew[e] : scal[1];
        a += ea * cvec[hd];
    }
    a = a > 0.f ? a : 0.2f * a;   // leaky_relu 0.2
    alpha[idx] = a;
    atomic_max_f(&m[d * H + hd], a);
}

__global__ void k_gat_exp(const int* __restrict__ dst, float* __restrict__ alpha,
                          const float* __restrict__ m, float* __restrict__ den,
                          int E, int n, int H) {
    int idx = blockIdx.x * blockDim.x + threadIdx.x;
    if (idx >= (E + n) * H) return;
    int e = idx / H, hd = idx - e * H;
    int d = (e < E) ? dst[e] : (e - E);
    float p = __expf(alpha[idx] - m[d * H + hd]);
    alpha[idx] = p;
    atomicAdd(&den[d * H + hd], p);
}

// warp per destination node; accumulates ALL heads into one float4/lane
// (mean over heads shares the feature index), writes out row once.
template <int H>
__global__ void k_gat_gather(const float* __restrict__ h, const int* __restrict__ src,
                             const float* __restrict__ alpha, const float* __restrict__ den,
                             const int* __restrict__ offs, const int* __restrict__ eid,
                             float* __restrict__ out, int n, int E) {
    int t = blockIdx.x * blockDim.x + threadIdx.x;
    int d = t >> 5, lane = t & 31;
    if (d >= n) return;
    float rden[H];
#pragma unroll
    for (int hd = 0; hd < H; hd++) rden[hd] = 1.f / den[d * H + hd];
    float4 acc = make_float4(0.f, 0.f, 0.f, 0.f);
#pragma unroll
    for (int hd = 0; hd < H; hd++) {   // self-loop term
        float c = alpha[(size_t)(E + d) * H + hd] * rden[hd];
        float4 v = ((const float4*)(h + ((size_t)d * H + hd) * FD))[lane];
        acc.x += c * v.x; acc.y += c * v.y; acc.z += c * v.z; acc.w += c * v.w;
    }
    int b = offs[d], e_end = offs[d + 1];
    for (int i = b; i < e_end; ++i) {
        int e = eid[i];
        int s = src[e];
#pragma unroll
        for (int hd = 0; hd < H; hd++) {
            float c = alpha[(size_t)e * H + hd] * rden[hd];
            float4 v = ((const float4*)(h + ((size_t)s * H + hd) * FD))[lane];
            acc.x += c * v.x; acc.y += c * v.y; acc.z += c * v.z; acc.w += c * v.w;
        }
    }
    const float invH = 1.f / (float)H;
    acc.x *= invH; acc.y *= invH; acc.z *= invH; acc.w *= invH;
    ((float4*)(out + (size_t)d * FD))[lane] = acc;
}

// l = relu((gcn + bg + gat + ba)/2)
__global__ void k_combine(const float* __restrict__ gcn, const float* __restrict__ gat,
                          const float* __restrict__ bg, const float* __restrict__ ba,
                          float* __restrict__ o, long n128) {
    long i = (long)blockIdx.x * blockDim.x + threadIdx.x;
    if (i < n128) {
        int f = (int)(i & (FD - 1));
        float v = (gcn[i] + bg[f] + gat[i] + ba[f]) * 0.5f;
        o[i] = v > 0.f ? v : 0.f;
    }
}

// cat[n, 0:128]=a row, cat[n, 128:256]=b row
__global__ void k_cat(const float* __restrict__ a, const float* __restrict__ b,
                      float* __restrict__ o, long n256) {
    long i = (long)blockIdx.x * blockDim.x + threadIdx.x;
    if (i < n256) {
        long node = i >> 8;
        int f = (int)(i & 255);
        o[i] = (f < FD) ? a[node * FD + f] : b[node * FD + (f - FD)];
    }
}

// ------------------------- tiled SGEMM (double-buffered, fp32) -------------------------
// C[M,N] = A[M,K] @ op(B) (+bias[n]); TB=0: B is [K,N] row-major; TB=1: B is [N,K] row-major.
template <bool TB>
__global__ __launch_bounds__(256, 2) void k_sgemm(const float* __restrict__ A,
                                                  const float* __restrict__ B,
                                                  float* __restrict__ C, int M, int N, int K,
                                                  const float* __restrict__ bias) {
    __shared__ float As[2][16][128];
    __shared__ float Bs[2][16][128];
    const int m0 = blockIdx.y * 128;
    const int n0 = blockIdx.x * 128;
    const int tid = threadIdx.x;
    const int tx = tid & 15, ty = tid >> 4;
    const int rA = tid >> 2;          // 0..63
    const int kq = (tid & 3) << 2;    // 0,4,8,12
    const int kr = tid >> 5;          // 0..7   (TB=false B path)
    const int c4 = (tid & 31) << 2;   // 0..124 (TB=false B path)
    float acc[8][8] = {};
    float4 va[2], vb[2];

    auto load_tile = [&](int k0) {
#pragma unroll
        for (int hh = 0; hh < 2; hh++) {
            int gm = m0 + rA + hh * 64;
            va[hh] = make_float4(0.f, 0.f, 0.f, 0.f);
            if (gm < M) va[hh] = *(const float4*)(A + (size_t)gm * K + k0 + kq);
        }
        if (TB) {
#pragma unroll
            for (int hh = 0; hh < 2; hh++) {
                int gn = n0 + rA + hh * 64;
                vb[hh] = make_float4(0.f, 0.f, 0.f, 0.f);
                if (gn < N) vb[hh] = *(const float4*)(B + (size_t)gn * K + k0 + kq);
            }
        } else {
#pragma unroll
            for (int hh = 0; hh < 2; hh++) {
                int kk = kr + hh * 8;
                int gn = n0 + c4;
                float4 v = make_float4(0.f, 0.f, 0.f, 0.f);
                if (gn + 3 < N) {
                    v = *(const float4*)(B + (size_t)(k0 + kk) * N + gn);
                } else {
                    if (gn + 0 < N) v.x = B[(size_t)(k0 + kk) * N + gn + 0];
                    if (gn + 1 < N) v.y = B[(size_t)(k0 + kk) * N + gn + 1];
                    if (gn + 2 < N) v.z = B[(size_t)(k0 + kk) * N + gn + 2];
                    if (gn + 3 < N) v.w = B[(size_t)(k0 + kk) * N + gn + 3];
                }
                vb[hh] = v;
            }
        }
    };
    auto store_tile = [&](int buf) {
#pragma unroll
        for (int hh = 0; hh < 2; hh++) {
            int mm = rA + hh * 64;
            As[buf][kq + 0][mm] = va[hh].x; As[buf][kq + 1][mm] = va[hh].y;
            As[buf][kq + 2][mm] = va[hh].z; As[buf][kq + 3][mm] = va[hh].w;
        }
        if (TB) {
#pragma unroll
            for (int hh = 0; hh < 2; hh++) {
                int nn = rA + hh * 64;
                Bs[buf][kq + 0][nn] = vb[hh].x; Bs[buf][kq + 1][nn] = vb[hh].y;
                Bs[buf][kq + 2][nn] = vb[hh].z; Bs[buf][kq + 3][nn] = vb[hh].w;
            }
        } else {
#pragma unroll
            for (int hh = 0; hh < 2; hh++) {
                int kk = kr + hh * 8;
                Bs[buf][kk][c4 + 0] = vb[hh].x; Bs[buf][kk][c4 + 1] = vb[hh].y;
                Bs[buf][kk][c4 + 2] = vb[hh].z; Bs[buf][kk][c4 + 3] = vb[hh].w;
            }
        }
    };

    const int nk = K >> 4;
    load_tile(0);
    int buf = 0;
    for (int it = 0; it < nk; ++it) {
        store_tile(buf);
        __syncthreads();
        if (it + 1 < nk) load_tile((it + 1) << 4);   // overlap next global load with compute
#pragma unroll
        for (int k = 0; k < 16; k++) {
            float a[8], b[8];
            *(float4*)(a)     = *(const float4*)(&As[buf][k][ty * 8]);
            *(float4*)(a + 4) = *(const float4*)(&As[buf][k][ty * 8 + 4]);
            *(float4*)(b)     = *(const float4*)(&Bs[buf][k][tx * 8]);
            *(float4*)(b + 4) = *(const float4*)(&Bs[buf][k][tx * 8 + 4]);
#pragma unroll
            for (int i = 0; i < 8; i++)
#pragma unroll
                for (int j = 0; j < 8; j++)
                    acc[i][j] += a[i] * b[j];
        }
        buf ^= 1;
        // next iteration writes the OTHER buffer; per-iteration barrier bounds skew.
    }
#pragma unroll
    for (int i = 0; i < 8; i++) {
        int gm = m0 + ty * 8 + i;
        if (gm >= M) continue;
#pragma unroll
        for (int j = 0; j < 8; j += 4) {
            int gn = n0 + tx * 8 + j;
            if (gn + 3 < N) {
                float4 v = make_float4(acc[i][j], acc[i][j + 1], acc[i][j + 2], acc[i][j + 3]);
                if (bias) { v.x += bias[gn]; v.y += bias[gn + 1]; v.z += bias[gn + 2]; v.w += bias[gn + 3]; }
                *(float4*)(C + (size_t)gm * N + gn) = v;
            } else {
                for (int q = 0; q < 4; q++) {
                    int g = gn + q;
                    if (g < N) {
                        float v = acc[i][j + q];
                        if (bias) v += bias[g];
                        C[(size_t)gm * N + g] = v;
                    }
                }
            }
        }
    }
}

// ------------------------- TF32 tensor-core GEMMs (cp.async double-buffered) ---------
// 256 threads = 8 warps (2 x 4), warp tile 64x32, CTA tile 128x128, BK=32.
// Raw fp32 bits staged in smem; cvt.rna.tf32 applied at fragment load (rna preserved).
// A/B(NT) smem layout: [row][36] (pad 36 -> fragment bank = 4*gid+tig, conflict-free).
// B(NN) smem layout: [k][136] (pad 136 -> fragment bank = 8*tig+gid, conflict-free).
#define A_STRIDE 36
#define A_BUF    4608          // 128*36 words
#define BNN_STRIDE 136
#define BNN_BUF  4352          // 32*136 words
#define NT_DYN_BYTES (4 * A_BUF * 4)                   // 73728
#define NN_DYN_BYTES ((2 * A_BUF + 2 * BNN_BUF) * 4)   // 71680

// NT: C[M,N] = A[M,K] @ B[N,K]^T. K % 32 == 0.
__global__ __launch_bounds__(256, 2) void k_tgemm_nt(const float* __restrict__ A,
                                                     const float* __restrict__ B,
                                                     float* __restrict__ C,
                                                     int M, int N, int K) {
    extern __shared__ unsigned dyn[];
    const int m0 = blockIdx.y * 128;
    const int n0 = blockIdx.x * 128;
    const int tid = threadIdx.x;
    const int wid = tid >> 5, lane = tid & 31;
    const int wm = wid >> 2, wn = wid & 3;          // 2 x 4 warp grid
    const int gid = lane >> 2, tig = lane & 3;      // mma fragment coords
    const int mwb = wm * 64, nwb = wn * 32;

    float c[4][4][4] = {};
    const int nk = K >> 5;

    auto load_async = [&](int kc, int sbuf) {
        int k0 = kc << 5;
        unsigned* Asb = dyn + sbuf * A_BUF;
        unsigned* Bsb = dyn + 2 * A_BUF + sbuf * A_BUF;
#pragma unroll
        for (int i = 0; i < 4; i++) {
            int cA = tid + 256 * i;                 // 0..1023
            int row = cA >> 3;                      // 0..127
            int kq = (cA & 7) << 2;                 // 0,4,...,28
            int gm = m0 + row;
            bool va = gm < M;
            cp16(Asb + row * A_STRIDE + kq, A + (size_t)(va ? gm : 0) * K + k0 + kq, va);
            int gn = n0 + row;
            bool vb = gn < N;
            cp16(Bsb + row * A_STRIDE + kq, B + (size_t)(vb ? gn : 0) * K + k0 + kq, vb);
        }
        CP_COMMIT();
    };

    load_async(0, 0);
    for (int it = 0; it < nk; ++it) {
        int sbuf = it & 1;
        if (it + 1 < nk) { load_async(it + 1, sbuf ^ 1); CP_WAIT1(); }
        else             { CP_WAIT0(); }
        __syncthreads();
        const unsigned* Asb = dyn + sbuf * A_BUF;
        const unsigned* Bsb = dyn + 2 * A_BUF + sbuf * A_BUF;
#pragma unroll
        for (int ks = 0; ks < 32; ks += 8) {
            unsigned af[4][4], bf[4][2];
#pragma unroll
            for (int mt = 0; mt < 4; mt++) {
                int mb = mwb + mt * 16 + gid;
                af[mt][0] = f2tf32(__uint_as_float(Asb[mb * A_STRIDE + ks + tig]));
                af[mt][1] = f2tf32(__uint_as_float(Asb[(mb + 8) * A_STRIDE + ks + tig]));
                af[mt][2] = f2tf32(__uint_as_float(Asb[mb * A_STRIDE + ks + tig + 4]));
                af[mt][3] = f2tf32(__uint_as_float(Asb[(mb + 8) * A_STRIDE + ks + tig + 4]));
            }
#pragma unroll
            for (int nt = 0; nt < 4; nt++) {
                int nb = nwb + nt * 8 + gid;
                bf[nt][0] = f2tf32(__uint_as_float(Bsb[nb * A_STRIDE + ks + tig]));
                bf[nt][1] = f2tf32(__uint_as_float(Bsb[nb * A_STRIDE + ks + tig + 4]));
            }
#pragma unroll
            for (int mt = 0; mt < 4; mt++)
#pragma unroll
                for (int nt = 0; nt < 4; nt++)
                    mma_tf32(c[mt][nt], af[mt][0], af[mt][1], af[mt][2], af[mt][3],
                             bf[nt][0], bf[nt][1]);
        }
        __syncthreads();   // all warps done with sbuf before next iter's load overwrites it
    }
#pragma unroll
    for (int mt = 0; mt < 4; mt++) {
        int gm0 = m0 + mwb + mt * 16 + gid;
#pragma unroll
        for (int nt = 0; nt < 4; nt++) {
            int gn = n0 + nwb + nt * 8 + 2 * tig;
            if (gn < N) {   // gn even & N even -> gn+1 < N too
                if (gm0 < M)
                    *(float2*)(C + (size_t)gm0 * N + gn) = make_float2(c[mt][nt][0], c[mt][nt][1]);
                if (gm0 + 8 < M)
                    *(float2*)(C + (size_t)(gm0 + 8) * N + gn) = make_float2(c[mt][nt][2], c[mt][nt][3]);
            }
        }
    }
}

// NN: C[M,N] = A[M,K] @ B[K,N], B row-major. K % 32 == 0, N % 4 == 0.
__global__ __launch_bounds__(256, 2) void k_tgemm_nn(const float* __restrict__ A,
                                                     const float* __restrict__ B,
                                                     float* __restrict__ C,
                                                     int M, int N, int K) {
    extern __shared__ unsigned dyn[];
    const int m0 = blockIdx.y * 128;
    const int n0 = blockIdx.x * 128;
    const int tid = threadIdx.x;
    const int wid = tid >> 5, lane = tid & 31;
    const int wm = wid >> 2, wn = wid & 3;
    const int gid = lane >> 2, tig = lane & 3;
    const int mwb = wm * 64, nwb = wn * 32;

    float c[4][4][4] = {};
    const int nk = K >> 5;

    auto load_async = [&](int kc, int sbuf) {
        int k0 = kc << 5;
        unsigned* Asb = dyn + sbuf * A_BUF;
        unsigned* Bsb = dyn + 2 * A_BUF + sbuf * BNN_BUF;
#pragma unroll
        for (int i = 0; i < 4; i++) {
            int cA = tid + 256 * i;
            int row = cA >> 3;
            int kq = (cA & 7) << 2;
            int gm = m0 + row;
            bool va = gm < M;
            cp16(Asb + row * A_STRIDE + kq, A + (size_t)(va ? gm : 0) * K + k0 + kq, va);
            int krow = cA >> 5;                     // 0..31
            int n4 = (cA & 31) << 2;                // 0..124
            int gn = n0 + n4;
            bool vb = gn + 3 < N;
            cp16(Bsb + krow * BNN_STRIDE + n4, B + (size_t)(k0 + krow) * N + (vb ? gn : 0), vb);
        }
        CP_COMMIT();
    };

    load_async(0, 0);
    for (int it = 0; it < nk; ++it) {
        int sbuf = it & 1;
        if (it + 1 < nk) { load_async(it + 1, sbuf ^ 1); CP_WAIT1(); }
        else             { CP_WAIT0(); }
        __syncthreads();
        const unsigned* Asb = dyn + sbuf * A_BUF;
        const unsigned* Bsb = dyn + 2 * A_BUF + sbuf * BNN_BUF;
#pragma unroll
        for (int ks = 0; ks < 32; ks += 8) {
            unsigned af[4][4], bf[4][2];
#pragma unroll
            for (int mt = 0; mt < 4; mt++) {
                int mb = mwb + mt * 16 + gid;
                af[mt][0] = f2tf32(__uint_as_float(Asb[mb * A_STRIDE + ks + tig]));
                af[mt][1] = f2tf32(__uint_as_float(Asb[(mb + 8) * A_STRIDE + ks + tig]));
                af[mt][2] = f2tf32(__uint_as_float(Asb[mb * A_STRIDE + ks + tig + 4]));
                af[mt][3] = f2tf32(__uint_as_float(Asb[(mb + 8) * A_STRIDE + ks + tig + 4]));
            }
#pragma unroll
            for (int nt = 0; nt < 4; nt++) {
                int nb = nwb + nt * 8 + gid;
                bf[nt][0] = f2tf32(__uint_as_float(Bsb[(ks + tig) * BNN_STRIDE + nb]));
                bf[nt][1] = f2tf32(__uint_as_float(Bsb[(ks + tig + 4) * BNN_STRIDE + nb]));
            }
#pragma unroll
            for (int mt = 0; mt < 4; mt++)
#pragma unroll
                for (int nt = 0; nt < 4; nt++)
                    mma_tf32(c[mt][nt], af[mt][0], af[mt][1], af[mt][2], af[mt][3],
                             bf[nt][0], bf[nt][1]);
        }
        __syncthreads();
    }
#pragma unroll
    for (int mt = 0; mt < 4; mt++) {
        int gm0 = m0 + mwb + mt * 16 + gid;
#pragma unroll
        for (int nt = 0; nt < 4; nt++) {
            int gn = n0 + nwb + nt * 8 + 2 * tig;
            if (gn + 1 < N) {
                if (gm0 < M)
                    *(float2*)(C + (size_t)gm0 * N + gn) = make_float2(c[mt][nt][0], c[mt][nt][1]);
                if (gm0 + 8 < M)
                    *(float2*)(C + (size_t)(gm0 + 8) * N + gn) = make_float2(c[mt][nt][2], c[mt][nt][3]);
            }
        }
    }
}

// ------------------------- host orchestration -------------------------
static inline unsigned gb(long n, int t) { return (unsigned)((n + t - 1) / t); }

extern "C" void kernel_launch(void* const* d_in, const int* in_sizes, int n_in,
                              void* d_out, int out_size) {
    (void)in_sizes; (void)n_in; (void)out_size;
    const float* x_drug = (const float*)d_in[0];
    const float* x_cir  = (const float*)d_in[1];
    const int*   dei    = (const int*)d_in[2];
    const int*   cei    = (const int*)d_in[3];
    const float* dew    = (const float*)d_in[4];
    const float* cew    = (const float*)d_in[5];
    const float* Wg1_d = (const float*)d_in[6];  const float* bg1_d = (const float*)d_in[7];
    const float* Wg2_d = (const float*)d_in[8];  const float* bg2_d = (const float*)d_in[9];
    const float* Wa_d  = (const float*)d_in[10]; const float* as_d  = (const float*)d_in[11];
    const float* ad_d  = (const float*)d_in[12]; const float* We_d  = (const float*)d_in[13];
    const float* ae_d  = (const float*)d_in[14]; const float* ba_d  = (const float*)d_in[15];
    const float* Wg1_c = (const float*)d_in[16]; const float* bg1_c = (const float*)d_in[17];
    const float* Wg2_c = (const float*)d_in[18]; const float* bg2_c = (const float*)d_in[19];
    const float* Wa_c  = (const float*)d_in[20]; const float* as_c  = (const float*)d_in[21];
    const float* ad_c  = (const float*)d_in[22]; const float* ba_c  = (const float*)d_in[23];
    const float* Kd    = (const float*)d_in[24]; const float* bKd   = (const float*)d_in[25];
    const float* Kc    = (const float*)d_in[26]; const float* bKc   = (const float*)d_in[27];
    float* out = (float*)d_out;

    const int* src_d = dei;       const int* dst_d = dei + ED_;
    const int* src_c = cei;       const int* dst_c = cei + EC_;

    static bool attr_done = false;
    if (!attr_done) {
        cudaFuncSetAttribute(k_tgemm_nt, cudaFuncAttributeMaxDynamicSharedMemorySize, NT_DYN_BYTES);
        cudaFuncSetAttribute(k_tgemm_nn, cudaFuncAttributeMaxDynamicSharedMemorySize, NN_DYN_BYTES);
        attr_done = true;
    }

    float *p_h, *p_gcn, *p_gat, *p_deg, *p_dinv_d, *p_dinv_c, *p_asum, *p_dsum;
    float *p_m, *p_den, *p_alpha, *p_scal, *p_cvec;
    float *p_l1d, *p_l2d, *p_l1c, *p_l2c, *p_cat, *p_dfea, *p_cfea;
    int *p_cnt, *p_offs, *p_cursor, *p_eid_d, *p_eid_c;
    cudaGetSymbolAddress((void**)&p_h, g_h);
    cudaGetSymbolAddress((void**)&p_gcn, g_gcn);
    cudaGetSymbolAddress((void**)&p_gat, g_gat);
    cudaGetSymbolAddress((void**)&p_deg, g_deg);
    cudaGetSymbolAddress((void**)&p_dinv_d, g_dinv_d);
    cudaGetSymbolAddress((void**)&p_dinv_c, g_dinv_c);
    cudaGetSymbolAddress((void**)&p_asum, g_asum);
    cudaGetSymbolAddress((void**)&p_dsum, g_dsum);
    cudaGetSymbolAddress((void**)&p_m, g_m);
    cudaGetSymbolAddress((void**)&p_den, g_den);
    cudaGetSymbolAddress((void**)&p_alpha, g_alpha);
    cudaGetSymbolAddress((void**)&p_scal, g_scal);
    cudaGetSymbolAddress((void**)&p_cvec, g_cvec);
    cudaGetSymbolAddress((void**)&p_l1d, g_l1d);
    cudaGetSymbolAddress((void**)&p_l2d, g_l2d);
    cudaGetSymbolAddress((void**)&p_l1c, g_l1c);
    cudaGetSymbolAddress((void**)&p_l2c, g_l2c);
    cudaGetSymbolAddress((void**)&p_cat, g_cat);
    cudaGetSymbolAddress((void**)&p_dfea, g_dfea);
    cudaGetSymbolAddress((void**)&p_cfea, g_cfea);
    cudaGetSymbolAddress((void**)&p_cnt, g_cnt);
    cudaGetSymbolAddress((void**)&p_offs, g_offs);
    cudaGetSymbolAddress((void**)&p_cursor, g_cursor);
    cudaGetSymbolAddress((void**)&p_eid_d, g_eid_d);
    cudaGetSymbolAddress((void**)&p_eid_c, g_eid_c);

    auto fill = [](float* p, float v, long n) {
        k_fill<<<gb(n, 256), 256>>>(p, v, n);
    };
    auto tgemm_nn = [](const float* A, const float* B, float* C, int M, int N, int K) {
        dim3 grid((N + 127) / 128, (M + 127) / 128);
        k_tgemm_nn<<<grid, 256, NN_DYN_BYTES>>>(A, B, C, M, N, K);
    };
    auto build_csr = [&](const int* dst, int E, int n, int* eid) {
        k_ifill<<<gb(n, 256), 256>>>(p_cnt, 0, n);
        k_hist<<<gb(E, 256), 256>>>(dst, p_cnt, E);
        k_scan<<<1, 1024>>>(p_cnt, p_offs, p_cursor, n);
        k_place<<<gb(E, 256), 256>>>(dst, p_cursor, eid, E);
    };

    auto run_gcn = [&](const float* x, const float* Wg, const int* src,
                       const float* ew, const float* dinv, const int* eid,
                       float* outb, int n) {
        tgemm_nn(x, Wg, p_h, n, FD, FD);
        k_gcn_gather<<<gb((long)n * 32, 256), 256>>>(p_h, src, ew, dinv, p_offs, eid, outb, n);
    };

    auto run_gat = [&](const float* x, const float* Wa, const float* as_, const float* ad_,
                       const int* src, const int* dst, const float* ew, bool edge_attr,
                       const int* eid, float* outb, int n, int E, int H) {
        tgemm_nn(x, Wa, p_h, n, H * FD, FD);
        int nH = n * H;
        k_gat_node<<<gb((long)nH * 32, 256), 256>>>(p_h, as_, ad_, p_asum, p_dsum, nH, H);
        fill(p_m, -INFINITY, nH);
        fill(p_den, 0.f, nH);
        long tot = (long)(E + n) * H;
        k_gat_alpha<<<gb(tot, 256), 256>>>(src, dst, ew, p_scal, edge_attr ? p_cvec : nullptr,
                                           p_asum, p_dsum, p_alpha, p_m, E, n, H);
        k_gat_exp<<<gb(tot, 256), 256>>>(dst, p_alpha, p_m, p_den, E, n, H);
        if (H == 4)
            k_gat_gather<4><<<gb((long)n * 32, 256), 256>>>(p_h, src, p_alpha, p_den,
                                                            p_offs, eid, outb, n, E);
        else
            k_gat_gather<1><<<gb((long)n * 32, 256), 256>>>(p_h, src, p_alpha, p_den,
                                                            p_offs, eid, outb, n, E);
    };

    auto combine = [&](const float* bg, const float* ba, float* l, int n) {
        long n128 = (long)n * FD;
        k_combine<<<gb(n128, 256), 256>>>(p_gcn, p_gat, bg, ba, l, n128);
    };

    // ---- per-graph invariants: degree / symmetric-norm; edge-attn mean + coeffs ----
    fill(p_deg, 1.f, ND);                                    // self-loop weight 1
    k_deg<<<gb(ED_, 256), 256>>>(dst_d, dew, p_deg, ED_);
    k_dinv<<<gb(ND, 256), 256>>>(p_deg, p_dinv_d, ND);
    fill(p_deg, 1.f, NC);
    k_deg<<<gb(EC_, 256), 256>>>(dst_c, cew, p_deg, EC_);
    k_dinv<<<gb(NC, 256), 256>>>(p_deg, p_dinv_c, NC);
    fill(p_scal, 0.f, 2);
    k_sum<<<256, 256>>>(dew, p_scal, ED_);
    k_gat_prep<<<1, 128>>>(We_d, ae_d, p_scal, p_cvec, 1.f / (float)ED_);

    // ---- drug graph: CSR + 2 layers ----
    build_csr(dst_d, ED_, ND, p_eid_d);
    run_gcn(x_drug, Wg1_d, src_d, dew, p_dinv_d, p_eid_d, p_gcn, ND);
    run_gat(x_drug, Wa_d, as_d, ad_d, src_d, dst_d, dew, true, p_eid_d, p_gat, ND, ED_, NH);
    combine(bg1_d, ba_d, p_l1d, ND);
    run_gcn(p_l1d, Wg2_d, src_d, dew, p_dinv_d, p_eid_d, p_gcn, ND);
    run_gat(p_l1d, Wa_d, as_d, ad_d, src_d, dst_d, dew, true, p_eid_d, p_gat, ND, ED_, NH);
    combine(bg2_d, ba_d, p_l2d, ND);

    // ---- circ graph: CSR (offs rebuilt) + 2 layers ----
    build_csr(dst_c, EC_, NC, p_eid_c);
    run_gcn(x_cir, Wg1_c, src_c, cew, p_dinv_c, p_eid_c, p_gcn, NC);
    run_gat(x_cir, Wa_c, as_c, ad_c, src_c, dst_c, nullptr, false, p_eid_c, p_gat, NC, EC_, 1);
    combine(bg1_c, ba_c, p_l1c, NC);
    run_gcn(p_l1c, Wg2_c, src_c, cew, p_dinv_c, p_eid_c, p_gcn, NC);
    run_gat(p_l1c, Wa_c, as_c, ad_c, src_c, dst_c, nullptr, false, p_eid_c, p_gat, NC, EC_, 1);
    combine(bg2_c, ba_c, p_l2c, NC);

    // ---- CNN fuse: fea = [l1 | l2] @ Kflat^T + bK   (Kflat is [OC, 2F] row-major) ----
    k_cat<<<gb((long)ND * 256, 256), 256>>>(p_l1d, p_l2d, p_cat, (long)ND * 256);
    {
        dim3 grid((OCD + 127) / 128, (ND + 127) / 128);
        k_sgemm<true><<<grid, 256>>>(p_cat, Kd, p_dfea, ND, OCD, 2 * FD, bKd);
    }
    k_cat<<<gb((long)NC * 256, 256), 256>>>(p_l1c, p_l2c, p_cat, (long)NC * 256);
    {
        dim3 grid((OCD + 127) / 128, (NC + 127) / 128);
        k_sgemm<true><<<grid, 256>>>(p_cat, Kc, p_cfea, NC, OCD, 2 * FD, bKc);
    }

    // ---- final: out[0 : NC*ND] = cir_fea @ drug_fea^T (TF32 tensor cores) ----
    {
        dim3 grid((ND + 127) / 128, (NC + 127) / 128);
        k_tgemm_nt<<<grid, 256, NT_DYN_BYTES>>>(p_cfea, p_dfea, out, NC, ND, FD);
    }
    long tail = (long)ND * OCD;
    k_copy<<<gb(tail, 256), 256>>>(p_dfea, out + (size_t)NC * ND, tail);
}